// round 9
// baseline (speedup 1.0000x reference)
#include <cuda_runtime.h>
#include <cuda_bf16.h>
#include <cstdint>
#include <cstddef>

// Problem dims (fixed)
#define BB 16
#define SS 2048
#define LL 256
#define HH 768
#define CC 512
#define MROWS (BB*SS)   // 32768

typedef __nv_bfloat16  bf16;
typedef __nv_bfloat162 bf162;

// ---------------- one static scratch pool, byte-addressed -------------------
constexpr size_t SZ_IT     = (size_t)MROWS * CC * 4;
constexpr size_t SZ_FP     = (size_t)512 * CC * 4;          // fpart[512][512]
constexpr size_t SZ_FU     = (size_t)BB * CC * 4;
constexpr size_t SZ_X2     = (size_t)MROWS * HH * 2;
constexpr size_t SZ_LAB2   = (size_t)LL * HH * 2;
constexpr size_t SZ_WT2    = (size_t)CC * HH * 2;
constexpr size_t SZ_IA2    = (size_t)MROWS * CC * 2;
constexpr size_t SZ_LC2    = (size_t)LL * CC * 2;

constexpr size_t OFF_IT     = 0;
constexpr size_t OFF_FP     = OFF_IT + SZ_IT;
constexpr size_t OFF_FU     = OFF_FP + SZ_FP;
constexpr size_t OFF_XH     = OFF_FU + SZ_FU;
constexpr size_t OFF_XL     = OFF_XH + SZ_X2;
constexpr size_t OFF_LABH   = OFF_XL + SZ_X2;
constexpr size_t OFF_LABL   = OFF_LABH + SZ_LAB2;
constexpr size_t OFF_WIH    = OFF_LABL + SZ_LAB2;
constexpr size_t OFF_WIL    = OFF_WIH + SZ_WT2;
constexpr size_t OFF_WLH    = OFF_WIL + SZ_WT2;
constexpr size_t OFF_WLL    = OFF_WLH + SZ_WT2;
constexpr size_t OFF_WIAH   = OFF_WLL + SZ_WT2;
constexpr size_t OFF_WIAL   = OFF_WIAH + SZ_WT2;
constexpr size_t OFF_WLAH   = OFF_WIAL + SZ_WT2;
constexpr size_t OFF_WLAL   = OFF_WLAH + SZ_WT2;
constexpr size_t OFF_IAH    = OFF_WLAL + SZ_WT2;
constexpr size_t OFF_IAL    = OFF_IAH + SZ_IA2;
constexpr size_t OFF_LTH    = OFF_IAL + SZ_IA2;
constexpr size_t OFF_LTL    = OFF_LTH + SZ_LC2;
constexpr size_t OFF_LAH    = OFF_LTL + SZ_LC2;
constexpr size_t OFF_LAL    = OFF_LAH + SZ_LC2;
constexpr size_t POOL_BYTES = OFF_LAL + SZ_LC2;

__device__ __align__(16) unsigned char g_pool[POOL_BYTES];

// ---------------- helpers ---------------------------------------------------
__device__ __forceinline__ uint32_t smem_u32(const void* p) {
    uint32_t a;
    asm("{ .reg .u64 t; cvta.to.shared.u64 t, %1; cvt.u32.u64 %0, t; }" : "=r"(a) : "l"(p));
    return a;
}
__device__ __forceinline__ void cp16(uint32_t dst, const void* src) {
    asm volatile("cp.async.cg.shared.global [%0], [%1], 16;" :: "r"(dst), "l"(src) : "memory");
}
__device__ __forceinline__ void cp32(uint32_t dst, const bf16* src) {
    cp16(dst, src);
    cp16(dst + 16, src + 8);
}
#define CP_COMMIT() asm volatile("cp.async.commit_group;" ::: "memory")
#define CP_WAIT0()  asm volatile("cp.async.wait_group 0;"  ::: "memory")

#define LDSM4(R0,R1,R2,R3,ADDR) \
    asm volatile("ldmatrix.sync.aligned.m8n8.x4.shared.b16 {%0,%1,%2,%3}, [%4];" \
                 : "=r"(R0),"=r"(R1),"=r"(R2),"=r"(R3) : "r"(ADDR))

#define MMA_BF16(C,A,B0,B1) \
    asm volatile("mma.sync.aligned.m16n8k16.row.col.f32.bf16.bf16.f32 " \
                 "{%0,%1,%2,%3},{%4,%5,%6,%7},{%8,%9},{%0,%1,%2,%3};" \
                 : "+f"((C)[0]),"+f"((C)[1]),"+f"((C)[2]),"+f"((C)[3]) \
                 : "r"((A)[0]),"r"((A)[1]),"r"((A)[2]),"r"((A)[3]), \
                   "r"(B0),"r"(B1))

__device__ __forceinline__ void bsplit(float v, bf16& h, bf16& l) {
    h = __float2bfloat16(v);
    l = __float2bfloat16(v - __bfloat162float(h));
}
__device__ __forceinline__ float sigmoidf_(float v) {
    return 1.0f / (1.0f + __expf(-v));
}

// ---------------- fp32 -> bf16 hi/lo split ----------------------------------
__global__ __launch_bounds__(256)
void ksplit(const float4* __restrict__ src, size_t oHi, size_t oLo, int n4)
{
    int i = blockIdx.x * 256 + threadIdx.x;
    if (i >= n4) return;
    bf162* hi = (bf162*)(g_pool + oHi);
    bf162* lo = (bf162*)(g_pool + oLo);
    float4 v = src[i];
    bf16 h0, l0, h1, l1, h2, l2, h3, l3;
    bsplit(v.x, h0, l0); bsplit(v.y, h1, l1);
    bsplit(v.z, h2, l2); bsplit(v.w, h3, l3);
    hi[i * 2 + 0] = __halves2bfloat162(h0, h1);
    hi[i * 2 + 1] = __halves2bfloat162(h2, h3);
    lo[i * 2 + 0] = __halves2bfloat162(l0, l1);
    lo[i * 2 + 1] = __halves2bfloat162(l2, l3);
}

// ---------------- shared tile geometry ---------------------------------------
#define SROW  80            // smem bytes per 32-bf16 row (64B data + 16B pad)
#define TILEB (128 * SROW)  // 10240

enum { EPI_NONE = 0, EPI_SIGC = 1, EPI_SIGC_SCALE = 2, EPI_SIGR = 3 };

// ---------------- single-output bf16-split mma GEMM (G1/G2) -------------------
#define STAGEB (4 * TILEB)
#define GSMEM (2 * STAGEB)  // 81920

template<int EPI>
__global__ __launch_bounds__(256, 2)
void mma_gemm(size_t oAh, size_t oAl, size_t oBh, size_t oBl,
              size_t oCh, size_t oCl,
              int M, int N, int K,
              const float* __restrict__ bias)
{
    const bf16* Ah = (const bf16*)(g_pool + oAh);
    const bf16* Al = (const bf16*)(g_pool + oAl);
    const bf16* Bh = (const bf16*)(g_pool + oBh);
    const bf16* Bl = (const bf16*)(g_pool + oBl);
    bf16* Ch  = (bf16*)(g_pool + oCh);
    bf16* Cl  = (bf16*)(g_pool + oCl);

    extern __shared__ char smem[];
    const uint32_t sb = smem_u32(smem);
    const int tid  = threadIdx.x;
    const int lane = tid & 31;
    const int wid  = tid >> 5;
    const int wm   = wid & 3;
    const int wn   = wid >> 2;
    const int m0 = blockIdx.y * 128;
    const int n0 = blockIdx.x * 128;

    const int lr = tid >> 1;
    const int lh = tid & 1;
    const bf16* gAh = Ah + (size_t)(m0 + lr) * K + lh * 16;
    const bf16* gAl = Al + (size_t)(m0 + lr) * K + lh * 16;
    const bf16* gBh = Bh + (size_t)(n0 + lr) * K + lh * 16;
    const bf16* gBl = Bl + (size_t)(n0 + lr) * K + lh * 16;
    const uint32_t sdst = (uint32_t)(lr * SROW + lh * 32);

    const int NCH = K / 32;
    float c[2][8][4] = {};

    {
        uint32_t d = sb + sdst;
        cp32(d,             gAh);
        cp32(d + TILEB,     gAl);
        cp32(d + 2 * TILEB, gBh);
        cp32(d + 3 * TILEB, gBl);
        CP_COMMIT();
        CP_WAIT0();
        __syncthreads();
    }

    for (int ch = 0; ch < NCH; ch++) {
        if (ch + 1 < NCH) {
            const int k0 = (ch + 1) * 32;
            uint32_t d = sb + ((ch + 1) & 1) * STAGEB + sdst;
            cp32(d,             gAh + k0);
            cp32(d + TILEB,     gAl + k0);
            cp32(d + 2 * TILEB, gBh + k0);
            cp32(d + 3 * TILEB, gBl + k0);
            CP_COMMIT();
        }

        const uint32_t base = sb + (ch & 1) * STAGEB;
        #pragma unroll
        for (int ks = 0; ks < 2; ks++) {
            uint32_t ah[2][4], al[2][4];
            #pragma unroll
            for (int mf = 0; mf < 2; mf++) {
                uint32_t addr = base
                    + (uint32_t)((wm * 32 + mf * 16 + (lane & 15)) * SROW)
                    + (uint32_t)(ks * 32 + (lane >> 4) * 16);
                LDSM4(ah[mf][0], ah[mf][1], ah[mf][2], ah[mf][3], addr);
                LDSM4(al[mf][0], al[mf][1], al[mf][2], al[mf][3], addr + TILEB);
            }
            const int g = lane >> 3;
            #pragma unroll
            for (int p = 0; p < 4; p++) {
                uint32_t addr = base + 2 * TILEB
                    + (uint32_t)((wn * 64 + p * 16 + ((g & 2) ? 8 : 0) + (lane & 7)) * SROW)
                    + (uint32_t)(ks * 32 + (g & 1) * 16);
                uint32_t h0, h1, h2, h3, l0, l1, l2, l3;
                LDSM4(h0, h1, h2, h3, addr);
                LDSM4(l0, l1, l2, l3, addr + TILEB);
                #pragma unroll
                for (int mf = 0; mf < 2; mf++) {
                    MMA_BF16(c[mf][2*p],   ah[mf], h0, h1);
                    MMA_BF16(c[mf][2*p],   ah[mf], l0, l1);
                    MMA_BF16(c[mf][2*p],   al[mf], h0, h1);
                    MMA_BF16(c[mf][2*p+1], ah[mf], h2, h3);
                    MMA_BF16(c[mf][2*p+1], ah[mf], l2, l3);
                    MMA_BF16(c[mf][2*p+1], al[mf], h2, h3);
                }
            }
        }
        if (ch + 1 < NCH) CP_WAIT0();
        __syncthreads();
    }

    const int quad = lane >> 2;
    const int tq   = lane & 3;
    #pragma unroll
    for (int mf = 0; mf < 2; mf++) {
        const int r0 = m0 + wm * 32 + mf * 16 + quad;
        const int r1 = r0 + 8;
        float rb0 = 0.f, rb1 = 0.f;
        if (EPI == EPI_SIGR) { rb0 = bias[r0]; rb1 = bias[r1]; }
        #pragma unroll
        for (int nf = 0; nf < 8; nf++) {
            const int col = n0 + wn * 64 + nf * 8 + tq * 2;
            float v0 = c[mf][nf][0], v1 = c[mf][nf][1];
            float v2 = c[mf][nf][2], v3 = c[mf][nf][3];
            if (EPI == EPI_SIGC) {
                float2 bb = *(const float2*)(bias + col);
                v0 = sigmoidf_(v0 + bb.x); v1 = sigmoidf_(v1 + bb.y);
                v2 = sigmoidf_(v2 + bb.x); v3 = sigmoidf_(v3 + bb.y);
            } else {
                v0 = sigmoidf_(v0 + rb0); v1 = sigmoidf_(v1 + rb0);
                v2 = sigmoidf_(v2 + rb1); v3 = sigmoidf_(v3 + rb1);
            }
            bf16 h0, l0, h1, l1;
            bsplit(v0, h0, l0); bsplit(v1, h1, l1);
            *(bf162*)(Ch + (size_t)r0 * N + col) = __halves2bfloat162(h0, h1);
            *(bf162*)(Cl + (size_t)r0 * N + col) = __halves2bfloat162(l0, l1);
            bsplit(v2, h0, l0); bsplit(v3, h1, l1);
            *(bf162*)(Ch + (size_t)r1 * N + col) = __halves2bfloat162(h0, h1);
            *(bf162*)(Cl + (size_t)r1 * N + col) = __halves2bfloat162(l0, l1);
        }
    }
}

// ---------------- fused dual GEMM: it + ia' from shared A --------------------
#define DSTAGEB (6 * TILEB)       // 61440
#define DGSMEM  (2 * DSTAGEB)     // 122880

__global__ __launch_bounds__(512, 1)
void mma_gemm_dual(const float* __restrict__ bias_i,
                   const float* __restrict__ bias_ia,
                   const float* __restrict__ ctx)
{
    extern __shared__ char smem[];
    const uint32_t sb = smem_u32(smem);
    const int tid  = threadIdx.x;
    const int lane = tid & 31;
    const int wid  = tid >> 5;
    const int wg   = wid >> 3;        // 0: it, 1: ia
    const int wl   = wid & 7;
    const int wm   = wl & 3;
    const int wn   = wl >> 2;
    const int m0 = blockIdx.y * 128;
    const int n0 = blockIdx.x * 128;
    const int K = HH;

    const bf16* srcp[3];
    uint32_t dstp[3];
    {
        const bf16* baseA_h = (const bf16*)(g_pool + OFF_XH);
        const bf16* baseA_l = (const bf16*)(g_pool + OFF_XL);
        const bf16* baseB0h = (const bf16*)(g_pool + OFF_WIH);
        const bf16* baseB0l = (const bf16*)(g_pool + OFF_WIL);
        const bf16* baseB1h = (const bf16*)(g_pool + OFF_WIAH);
        const bf16* baseB1l = (const bf16*)(g_pool + OFF_WIAL);
        #pragma unroll
        for (int t = 0; t < 3; t++) {
            int chunk = tid + t * 512;
            int tile = chunk >> 8;
            int pos  = chunk & 255;
            int row  = pos >> 1;
            int half = pos & 1;
            const bf16* bp;
            int rbase;
            switch (tile) {
                case 0: bp = baseA_h; rbase = m0; break;
                case 1: bp = baseA_l; rbase = m0; break;
                case 2: bp = baseB0h; rbase = n0; break;
                case 3: bp = baseB0l; rbase = n0; break;
                case 4: bp = baseB1h; rbase = n0; break;
                default: bp = baseB1l; rbase = n0; break;
            }
            srcp[t] = bp + (size_t)(rbase + row) * K + half * 16;
            dstp[t] = (uint32_t)(tile * TILEB + row * SROW + half * 32);
        }
    }

    const int NCH = K / 32;
    float c[2][8][4] = {};

    {
        #pragma unroll
        for (int t = 0; t < 3; t++)
            cp32(sb + dstp[t], srcp[t]);
        CP_COMMIT();
        CP_WAIT0();
        __syncthreads();
    }

    const uint32_t bofs = (uint32_t)((2 + 2 * wg) * TILEB);

    for (int ch = 0; ch < NCH; ch++) {
        if (ch + 1 < NCH) {
            const int k0 = (ch + 1) * 32;
            const uint32_t stg = sb + ((ch + 1) & 1) * DSTAGEB;
            #pragma unroll
            for (int t = 0; t < 3; t++)
                cp32(stg + dstp[t], srcp[t] + k0);
            CP_COMMIT();
        }

        const uint32_t base = sb + (ch & 1) * DSTAGEB;
        #pragma unroll
        for (int ks = 0; ks < 2; ks++) {
            uint32_t ah[2][4], al[2][4];
            #pragma unroll
            for (int mf = 0; mf < 2; mf++) {
                uint32_t addr = base
                    + (uint32_t)((wm * 32 + mf * 16 + (lane & 15)) * SROW)
                    + (uint32_t)(ks * 32 + (lane >> 4) * 16);
                LDSM4(ah[mf][0], ah[mf][1], ah[mf][2], ah[mf][3], addr);
                LDSM4(al[mf][0], al[mf][1], al[mf][2], al[mf][3], addr + TILEB);
            }
            const int g = lane >> 3;
            #pragma unroll
            for (int p = 0; p < 4; p++) {
                uint32_t addr = base + bofs
                    + (uint32_t)((wn * 64 + p * 16 + ((g & 2) ? 8 : 0) + (lane & 7)) * SROW)
                    + (uint32_t)(ks * 32 + (g & 1) * 16);
                uint32_t h0, h1, h2, h3, l0, l1, l2, l3;
                LDSM4(h0, h1, h2, h3, addr);
                LDSM4(l0, l1, l2, l3, addr + TILEB);
                #pragma unroll
                for (int mf = 0; mf < 2; mf++) {
                    MMA_BF16(c[mf][2*p],   ah[mf], h0, h1);
                    MMA_BF16(c[mf][2*p],   ah[mf], l0, l1);
                    MMA_BF16(c[mf][2*p],   al[mf], h0, h1);
                    MMA_BF16(c[mf][2*p+1], ah[mf], h2, h3);
                    MMA_BF16(c[mf][2*p+1], ah[mf], l2, l3);
                    MMA_BF16(c[mf][2*p+1], al[mf], h2, h3);
                }
            }
        }
        if (ch + 1 < NCH) CP_WAIT0();
        __syncthreads();
    }

    const int quad = lane >> 2;
    const int tq   = lane & 3;
    if (wg == 0) {
        float* Cf = (float*)(g_pool + OFF_IT);
        #pragma unroll
        for (int mf = 0; mf < 2; mf++) {
            const int r0 = m0 + wm * 32 + mf * 16 + quad;
            const int r1 = r0 + 8;
            #pragma unroll
            for (int nf = 0; nf < 8; nf++) {
                const int col = n0 + wn * 64 + nf * 8 + tq * 2;
                float2 bb = *(const float2*)(bias_i + col);
                float v0 = sigmoidf_(c[mf][nf][0] + bb.x);
                float v1 = sigmoidf_(c[mf][nf][1] + bb.y);
                float v2 = sigmoidf_(c[mf][nf][2] + bb.x);
                float v3 = sigmoidf_(c[mf][nf][3] + bb.y);
                *(float2*)(Cf + (size_t)r0 * CC + col) = make_float2(v0, v1);
                *(float2*)(Cf + (size_t)r1 * CC + col) = make_float2(v2, v3);
            }
        }
    } else {
        bf16* Ch = (bf16*)(g_pool + OFF_IAH);
        bf16* Cl = (bf16*)(g_pool + OFF_IAL);
        #pragma unroll
        for (int mf = 0; mf < 2; mf++) {
            const int r0 = m0 + wm * 32 + mf * 16 + quad;
            const int r1 = r0 + 8;
            #pragma unroll
            for (int nf = 0; nf < 8; nf++) {
                const int col = n0 + wn * 64 + nf * 8 + tq * 2;
                float2 bb = *(const float2*)(bias_ia + col);
                float2 ss = *(const float2*)(ctx + col);
                float v0 = sigmoidf_(c[mf][nf][0] + bb.x) * ss.x;
                float v1 = sigmoidf_(c[mf][nf][1] + bb.y) * ss.y;
                float v2 = sigmoidf_(c[mf][nf][2] + bb.x) * ss.x;
                float v3 = sigmoidf_(c[mf][nf][3] + bb.y) * ss.y;
                bf16 h0, l0, h1, l1;
                bsplit(v0, h0, l0); bsplit(v1, h1, l1);
                *(bf162*)(Ch + (size_t)r0 * CC + col) = __halves2bfloat162(h0, h1);
                *(bf162*)(Cl + (size_t)r0 * CC + col) = __halves2bfloat162(l0, l1);
                bsplit(v2, h0, l0); bsplit(v3, h1, l1);
                *(bf162*)(Ch + (size_t)r1 * CC + col) = __halves2bfloat162(h0, h1);
                *(bf162*)(Cl + (size_t)r1 * CC + col) = __halves2bfloat162(l0, l1);
            }
        }
    }
}

// ================= fused attention: logits -> softmax -> weighted -> fusion ==
// One CTA per 64 m-rows. 256 threads, 8 warps as 2(m) x 4(n).
#define FM 64
#define LSTRIDE 260                          // floats per logits smem row
#define SM_L 0
#define SZ_L (FM * LSTRIDE * 4)              // 66560
#define TA (FM * SROW)                       // 5120
#define TB (128 * SROW)                      // 10240
#define SM_T SZ_L
#define G1STAGE (2 * TA + 2 * TB)            // 30720
#define SZ_T (2 * G1STAGE)                   // 61440
#define SM_FACC (SM_T + SZ_T)                // 128000
#define FSMEM (SM_FACC + 2 * 128 * 4)        // 129024

__global__ __launch_bounds__(256, 1)
void attn_fused()
{
    extern __shared__ char smem[];
    const uint32_t sb = smem_u32(smem);
    const int tid  = threadIdx.x;
    const int lane = tid & 31;
    const int wid  = tid >> 5;
    const int wm   = wid & 1;       // 2 m-warps * 32 rows
    const int wn   = wid >> 1;      // 4 n-warps * 32 cols
    const int m0 = blockIdx.x * FM;
    const int quad = lane >> 2;
    const int tq   = lane & 3;

    const bf16* iah = (const bf16*)(g_pool + OFF_IAH);
    const bf16* ial = (const bf16*)(g_pool + OFF_IAL);
    const bf16* lah = (const bf16*)(g_pool + OFF_LAH);
    const bf16* lal = (const bf16*)(g_pool + OFF_LAL);
    const bf16* lth = (const bf16*)(g_pool + OFF_LTH);
    const float* itp = (const float*)(g_pool + OFF_IT);
    float* fpart = (float*)(g_pool + OFF_FP);
    float* facc  = (float*)(smem + SM_FACC);

    // ---- Phase 1: logits[64,256] = ia @ la^T, 3-product, two 128-col passes -
    const bf16* fsrc[3];
    uint32_t fdst[3];
    {
        if (tid < 128) {
            int row = tid >> 1, half = tid & 1;
            fsrc[0] = iah + (size_t)(m0 + row) * 512 + half * 16;
            fdst[0] = (uint32_t)(row * SROW + half * 32);
        } else {
            int idx = tid - 128, row = idx >> 1, half = idx & 1;
            fsrc[0] = ial + (size_t)(m0 + row) * 512 + half * 16;
            fdst[0] = (uint32_t)(TA + row * SROW + half * 32);
        }
        int row = tid >> 1, half = tid & 1;
        fsrc[1] = lah + (size_t)row * 512 + half * 16;
        fdst[1] = (uint32_t)(2 * TA + row * SROW + half * 32);
        fsrc[2] = lal + (size_t)row * 512 + half * 16;
        fdst[2] = (uint32_t)(2 * TA + TB + row * SROW + half * 32);
    }

    for (int pass = 0; pass < 2; pass++) {
        const int nb = pass * 128;
        const size_t bo = (size_t)nb * 512;
        float c[2][4][4] = {};

        {
            uint32_t s = sb + SM_T;
            cp32(s + fdst[0], fsrc[0]);
            cp32(s + fdst[1], fsrc[1] + bo);
            cp32(s + fdst[2], fsrc[2] + bo);
            CP_COMMIT();
            CP_WAIT0();
            __syncthreads();
        }

        for (int ch = 0; ch < 16; ch++) {
            if (ch + 1 < 16) {
                const int k0 = (ch + 1) * 32;
                uint32_t s = sb + SM_T + ((ch + 1) & 1) * G1STAGE;
                cp32(s + fdst[0], fsrc[0] + k0);
                cp32(s + fdst[1], fsrc[1] + bo + k0);
                cp32(s + fdst[2], fsrc[2] + bo + k0);
                CP_COMMIT();
            }
            const uint32_t base = sb + SM_T + (ch & 1) * G1STAGE;
            #pragma unroll
            for (int ks = 0; ks < 2; ks++) {
                uint32_t ah[2][4], al[2][4];
                #pragma unroll
                for (int mf = 0; mf < 2; mf++) {
                    uint32_t addr = base
                        + (uint32_t)((wm * 32 + mf * 16 + (lane & 15)) * SROW)
                        + (uint32_t)(ks * 32 + (lane >> 4) * 16);
                    LDSM4(ah[mf][0], ah[mf][1], ah[mf][2], ah[mf][3], addr);
                    LDSM4(al[mf][0], al[mf][1], al[mf][2], al[mf][3], addr + TA);
                }
                const int g = lane >> 3;
                #pragma unroll
                for (int p = 0; p < 2; p++) {
                    uint32_t addr = base + 2 * TA
                        + (uint32_t)((wn * 32 + p * 16 + ((g & 2) ? 8 : 0) + (lane & 7)) * SROW)
                        + (uint32_t)(ks * 32 + (g & 1) * 16);
                    uint32_t h0, h1, h2, h3, l0, l1, l2, l3;
                    LDSM4(h0, h1, h2, h3, addr);
                    LDSM4(l0, l1, l2, l3, addr + TB);
                    #pragma unroll
                    for (int mf = 0; mf < 2; mf++) {
                        MMA_BF16(c[mf][2*p],   ah[mf], h0, h1);
                        MMA_BF16(c[mf][2*p],   ah[mf], l0, l1);
                        MMA_BF16(c[mf][2*p],   al[mf], h0, h1);
                        MMA_BF16(c[mf][2*p+1], ah[mf], h2, h3);
                        MMA_BF16(c[mf][2*p+1], ah[mf], l2, l3);
                        MMA_BF16(c[mf][2*p+1], al[mf], h2, h3);
                    }
                }
            }
            if (ch + 1 < 16) CP_WAIT0();
            __syncthreads();
        }

        // write raw logits to smem
        #pragma unroll
        for (int mf = 0; mf < 2; mf++) {
            const int r0 = wm * 32 + mf * 16 + quad;
            const int r1 = r0 + 8;
            #pragma unroll
            for (int nf = 0; nf < 4; nf++) {
                const int col = nb + wn * 32 + nf * 8 + tq * 2;
                *(float2*)(smem + SM_L + (size_t)r0 * (LSTRIDE*4) + col * 4) =
                    make_float2(c[mf][nf][0], c[mf][nf][1]);
                *(float2*)(smem + SM_L + (size_t)r1 * (LSTRIDE*4) + col * 4) =
                    make_float2(c[mf][nf][2], c[mf][nf][3]);
            }
        }
        __syncthreads();
    }

    // ---- Phase 2: softmax rows, write attn bf16 into tile format (SM_T) -----
    {
        #pragma unroll
        for (int rr = 0; rr < 8; rr++) {
            const int r = wid * 8 + rr;
            const float* rowp = (const float*)(smem + SM_L + (size_t)r * (LSTRIDE*4));
            float v[8];
            float mx = -1e30f;
            #pragma unroll
            for (int j = 0; j < 8; j++) {
                v[j] = rowp[lane + 32 * j];
                mx = fmaxf(mx, v[j]);
            }
            #pragma unroll
            for (int s = 16; s > 0; s >>= 1)
                mx = fmaxf(mx, __shfl_xor_sync(0xffffffff, mx, s));
            float sum = 0.0f;
            #pragma unroll
            for (int j = 0; j < 8; j++) {
                v[j] = __expf(v[j] - mx);
                sum += v[j];
            }
            #pragma unroll
            for (int s = 16; s > 0; s >>= 1)
                sum += __shfl_xor_sync(0xffffffff, sum, s);
            const float inv = 1.0f / sum;
            #pragma unroll
            for (int j = 0; j < 8; j++) {
                *(bf16*)(smem + SM_T + j * TA + r * SROW
                         + ((lane >> 4) << 5) + (lane & 15) * 2)
                    = __float2bfloat16(v[j] * inv);
            }
        }
        __syncthreads();
    }

    // ---- Phase 3: weighted = attn @ lt^T (1-product), x it, row-reduce ------
    for (int p2 = 0; p2 < 4; p2++) {
        const int n0p = p2 * 128;
        const int brow = tid >> 1, bhalf = tid & 1;
        const bf16* bsrc = lth + (size_t)(n0p + brow) * 256 + bhalf * 16;
        const uint32_t bdst = (uint32_t)(brow * SROW + bhalf * 32);
        float c[2][4][4] = {};

        cp32(sb + SM_L + bdst, bsrc);
        CP_COMMIT();
        CP_WAIT0();
        __syncthreads();

        for (int ch = 0; ch < 8; ch++) {
            if (ch + 1 < 8) {
                cp32(sb + SM_L + ((ch + 1) & 1) * TB + bdst, bsrc + (ch + 1) * 32);
                CP_COMMIT();
            }
            const uint32_t abase = sb + SM_T + ch * TA;
            const uint32_t bbase = sb + SM_L + (ch & 1) * TB;
            #pragma unroll
            for (int ks = 0; ks < 2; ks++) {
                uint32_t ah[2][4];
                #pragma unroll
                for (int mf = 0; mf < 2; mf++) {
                    uint32_t addr = abase
                        + (uint32_t)((wm * 32 + mf * 16 + (lane & 15)) * SROW)
                        + (uint32_t)(ks * 32 + (lane >> 4) * 16);
                    LDSM4(ah[mf][0], ah[mf][1], ah[mf][2], ah[mf][3], addr);
                }
                const int g = lane >> 3;
                #pragma unroll
                for (int p = 0; p < 2; p++) {
                    uint32_t addr = bbase
                        + (uint32_t)((wn * 32 + p * 16 + ((g & 2) ? 8 : 0) + (lane & 7)) * SROW)
                        + (uint32_t)(ks * 32 + (g & 1) * 16);
                    uint32_t h0, h1, h2, h3;
                    LDSM4(h0, h1, h2, h3, addr);
                    #pragma unroll
                    for (int mf = 0; mf < 2; mf++) {
                        MMA_BF16(c[mf][2*p],   ah[mf], h0, h1);
                        MMA_BF16(c[mf][2*p+1], ah[mf], h2, h3);
                    }
                }
            }
            if (ch + 1 < 8) CP_WAIT0();
            __syncthreads();
        }

        // multiply by it and reduce over rows
        float pc[8];
        #pragma unroll
        for (int i = 0; i < 8; i++) pc[i] = 0.0f;
        #pragma unroll
        for (int mf = 0; mf < 2; mf++) {
            const int r0g = m0 + wm * 32 + mf * 16 + quad;
            const int r1g = r0g + 8;
            #pragma unroll
            for (int nf = 0; nf < 4; nf++) {
                const int colg = n0p + wn * 32 + nf * 8 + tq * 2;
                float2 i0 = *(const float2*)(itp + (size_t)r0g * CC + colg);
                float2 i1 = *(const float2*)(itp + (size_t)r1g * CC + colg);
                pc[2*nf]   += c[mf][nf][0] * i0.x + c[mf][nf][2] * i1.x;
                pc[2*nf+1] += c[mf][nf][1] * i0.y + c[mf][nf][3] * i1.y;
            }
        }
        #pragma unroll
        for (int off = 4; off <= 16; off <<= 1)
            #pragma unroll
            for (int i = 0; i < 8; i++)
                pc[i] += __shfl_xor_sync(0xffffffff, pc[i], off);
        if (quad == 0) {
            #pragma unroll
            for (int nf = 0; nf < 4; nf++) {
                const int col = wn * 32 + nf * 8 + tq * 2;
                facc[wm * 128 + col]     = pc[2*nf];
                facc[wm * 128 + col + 1] = pc[2*nf+1];
            }
        }
        __syncthreads();
        if (tid < 128) {
            fpart[(size_t)blockIdx.x * CC + n0p + tid] =
                facc[tid] + facc[128 + tid];
        }
        __syncthreads();
    }
}

// ---------------- fusion reduce: sum 32 blocks per batch ---------------------
__global__ __launch_bounds__(512)
void fusion_reduce()
{
    const float* fp = (const float*)(g_pool + OFF_FP);
    float* fu = (float*)(g_pool + OFF_FU);
    const int b = blockIdx.x, cidx = threadIdx.x;
    float acc = 0.0f;
    #pragma unroll
    for (int ns = 0; ns < 32; ns++)
        acc += fp[((size_t)b * 32 + ns) * CC + cidx];
    fu[(size_t)b * CC + cidx] = acc;
}

// ---------------- final: out[b,h] = sum_c fusion[b,c] * Wp[h,c] -------------
__global__ __launch_bounds__(256)
void final_gemm(const float* __restrict__ Wp, float* __restrict__ out)
{
    __shared__ float fs[CC];
    const float* fu = (const float*)(g_pool + OFF_FU);
    const int b = blockIdx.x;
    const int h = blockIdx.y * 256 + threadIdx.x;

    for (int i = threadIdx.x; i < CC; i += 256)
        fs[i] = fu[(size_t)b * CC + i];
    __syncthreads();

    float acc = 0.0f;
    const float4* wp4 = (const float4*)(Wp + (size_t)h * CC);
    const float4* fs4 = (const float4*)fs;
    #pragma unroll 4
    for (int c4 = 0; c4 < CC / 4; c4++) {
        float4 w = wp4[c4], f = fs4[c4];
        acc += w.x * f.x + w.y * f.y + w.z * f.z + w.w * f.w;
    }
    out[(size_t)b * HH + h] = acc;
}

// ---------------- launch ----------------------------------------------------
extern "C" void kernel_launch(void* const* d_in, const int* in_sizes, int n_in,
                              void* d_out, int out_size)
{
    const float* x   = (const float*)d_in[0];
    const float* lab = (const float*)d_in[1];
    const float* bi  = (const float*)d_in[3];
    const float* bl  = (const float*)d_in[5];
    const float* bia = (const float*)d_in[7];
    const float* bla = (const float*)d_in[9];
    const float* ctx = (const float*)d_in[10];
    const float* Wp  = (const float*)d_in[11];
    const float* Wi  = (const float*)d_in[2];
    const float* Wl  = (const float*)d_in[4];
    const float* Wia = (const float*)d_in[6];
    const float* Wla = (const float*)d_in[8];
    float* out = (float*)d_out;

    cudaFuncSetAttribute(mma_gemm<EPI_SIGR>, cudaFuncAttributeMaxDynamicSharedMemorySize, GSMEM);
    cudaFuncSetAttribute(mma_gemm<EPI_SIGC>, cudaFuncAttributeMaxDynamicSharedMemorySize, GSMEM);
    cudaFuncSetAttribute(mma_gemm_dual,      cudaFuncAttributeMaxDynamicSharedMemorySize, DGSMEM);
    cudaFuncSetAttribute(attn_fused,         cudaFuncAttributeMaxDynamicSharedMemorySize, FSMEM);

    // ---- input splits ----
    ksplit<<<(MROWS * HH / 4 + 255) / 256, 256>>>((const float4*)x,   OFF_XH,   OFF_XL,   MROWS * HH / 4);
    ksplit<<<(LL * HH / 4 + 255) / 256, 256>>>((const float4*)lab, OFF_LABH, OFF_LABL, LL * HH / 4);
    ksplit<<<(CC * HH / 4 + 255) / 256, 256>>>((const float4*)Wi,  OFF_WIH,  OFF_WIL,  CC * HH / 4);
    ksplit<<<(CC * HH / 4 + 255) / 256, 256>>>((const float4*)Wl,  OFF_WLH,  OFF_WLL,  CC * HH / 4);
    ksplit<<<(CC * HH / 4 + 255) / 256, 256>>>((const float4*)Wia, OFF_WIAH, OFF_WIAL, CC * HH / 4);
    ksplit<<<(CC * HH / 4 + 255) / 256, 256>>>((const float4*)Wla, OFF_WLAH, OFF_WLAL, CC * HH / 4);

    // ---- fused G3+G4: it (fp32) and ia' (split) from shared A ----
    mma_gemm_dual<<<dim3(CC / 128, MROWS / 128), 512, DGSMEM>>>(bi, bia, ctx);

    // ---- G1: ltT[c,l] = sigmoid(Wl @ lab^T + bl[row])  [512,256], K=768 ----
    mma_gemm<EPI_SIGR><<<dim3(LL / 128, CC / 128), 256, GSMEM>>>(
        OFF_WLH, OFF_WLL, OFF_LABH, OFF_LABL, OFF_LTH, OFF_LTL, CC, LL, HH, bl);

    // ---- G2: la[l,c] = sigmoid(lab @ Wla^T + bla[col]) [256,512], K=768 ----
    mma_gemm<EPI_SIGC><<<dim3(CC / 128, LL / 128), 256, GSMEM>>>(
        OFF_LABH, OFF_LABL, OFF_WLAH, OFF_WLAL, OFF_LAH, OFF_LAL, LL, CC, HH, bla);

    // ---- fused attention: logits -> softmax -> weighted -> fusion partials --
    attn_fused<<<MROWS / FM, 256, FSMEM>>>();

    // ---- fusion + final projection ----
    fusion_reduce<<<BB, 512>>>();
    final_gemm<<<dim3(BB, HH / 256), 256>>>(Wp, out);
}

// round 10
// speedup vs baseline: 1.2573x; 1.2573x over previous
#include <cuda_runtime.h>
#include <cuda_bf16.h>
#include <cstdint>
#include <cstddef>

// Problem dims (fixed)
#define BB 16
#define SS 2048
#define LL 256
#define HH 768
#define CC 512
#define MROWS (BB*SS)   // 32768

typedef __nv_bfloat16  bf16;
typedef __nv_bfloat162 bf162;

// ---------------- one static scratch pool, byte-addressed -------------------
constexpr size_t SZ_IT     = (size_t)MROWS * CC * 4;
constexpr size_t SZ_LOGITS = (size_t)MROWS * LL * 4;
constexpr size_t SZ_W      = (size_t)MROWS * CC * 4;
constexpr size_t SZ_FP     = (size_t)BB * 32 * CC * 4;
constexpr size_t SZ_FU     = (size_t)BB * CC * 4;
constexpr size_t SZ_X2     = (size_t)MROWS * HH * 2;
constexpr size_t SZ_LAB2   = (size_t)LL * HH * 2;
constexpr size_t SZ_WT2    = (size_t)CC * HH * 2;
constexpr size_t SZ_IA2    = (size_t)MROWS * CC * 2;
constexpr size_t SZ_ATT2   = (size_t)MROWS * LL * 2;
constexpr size_t SZ_LC2    = (size_t)LL * CC * 2;

constexpr size_t OFF_IT     = 0;
constexpr size_t OFF_LOGITS = OFF_IT + SZ_IT;
constexpr size_t OFF_W      = OFF_LOGITS + SZ_LOGITS;
constexpr size_t OFF_FP     = OFF_W + SZ_W;
constexpr size_t OFF_FU     = OFF_FP + SZ_FP;
constexpr size_t OFF_XH     = OFF_FU + SZ_FU;
constexpr size_t OFF_LABH   = OFF_XH + SZ_X2;
constexpr size_t OFF_LABL   = OFF_LABH + SZ_LAB2;
constexpr size_t OFF_WIH    = OFF_LABL + SZ_LAB2;
constexpr size_t OFF_WIL    = OFF_WIH + SZ_WT2;
constexpr size_t OFF_WLH    = OFF_WIL + SZ_WT2;
constexpr size_t OFF_WLL    = OFF_WLH + SZ_WT2;
constexpr size_t OFF_WIAH   = OFF_WLL + SZ_WT2;
constexpr size_t OFF_WIAL   = OFF_WIAH + SZ_WT2;
constexpr size_t OFF_WLAH   = OFF_WIAL + SZ_WT2;
constexpr size_t OFF_WLAL   = OFF_WLAH + SZ_WT2;
constexpr size_t OFF_IAH    = OFF_WLAL + SZ_WT2;
constexpr size_t OFF_IAL    = OFF_IAH + SZ_IA2;
constexpr size_t OFF_ATTH   = OFF_IAL + SZ_IA2;
constexpr size_t OFF_LTH    = OFF_ATTH + SZ_ATT2;
constexpr size_t OFF_LAH    = OFF_LTH + SZ_LC2;
constexpr size_t OFF_LAL    = OFF_LAH + SZ_LC2;
constexpr size_t POOL_BYTES = OFF_LAL + SZ_LC2;

__device__ __align__(16) unsigned char g_pool[POOL_BYTES];

// ---------------- helpers ---------------------------------------------------
__device__ __forceinline__ uint32_t smem_u32(const void* p) {
    uint32_t a;
    asm("{ .reg .u64 t; cvta.to.shared.u64 t, %1; cvt.u32.u64 %0, t; }" : "=r"(a) : "l"(p));
    return a;
}
__device__ __forceinline__ void cp16(uint32_t dst, const void* src) {
    asm volatile("cp.async.cg.shared.global [%0], [%1], 16;" :: "r"(dst), "l"(src) : "memory");
}
__device__ __forceinline__ void cp32(uint32_t dst, const bf16* src) {
    cp16(dst, src);
    cp16(dst + 16, src + 8);
}
#define CP_COMMIT() asm volatile("cp.async.commit_group;" ::: "memory")
#define CP_WAIT0()  asm volatile("cp.async.wait_group 0;"  ::: "memory")

#define LDSM4(R0,R1,R2,R3,ADDR) \
    asm volatile("ldmatrix.sync.aligned.m8n8.x4.shared.b16 {%0,%1,%2,%3}, [%4];" \
                 : "=r"(R0),"=r"(R1),"=r"(R2),"=r"(R3) : "r"(ADDR))

#define MMA_BF16(C,A,B0,B1) \
    asm volatile("mma.sync.aligned.m16n8k16.row.col.f32.bf16.bf16.f32 " \
                 "{%0,%1,%2,%3},{%4,%5,%6,%7},{%8,%9},{%0,%1,%2,%3};" \
                 : "+f"((C)[0]),"+f"((C)[1]),"+f"((C)[2]),"+f"((C)[3]) \
                 : "r"((A)[0]),"r"((A)[1]),"r"((A)[2]),"r"((A)[3]), \
                   "r"(B0),"r"(B1))

__device__ __forceinline__ void bsplit(float v, bf16& h, bf16& l) {
    h = __float2bfloat16(v);
    l = __float2bfloat16(v - __bfloat162float(h));
}
__device__ __forceinline__ float sigmoidf_(float v) {
    return 1.0f / (1.0f + __expf(-v));
}

// ---------------- fp32 -> bf16 splits ----------------------------------------
__global__ __launch_bounds__(256)
void ksplit(const float4* __restrict__ src, size_t oHi, size_t oLo, int n4)
{
    int i = blockIdx.x * 256 + threadIdx.x;
    if (i >= n4) return;
    bf162* hi = (bf162*)(g_pool + oHi);
    bf162* lo = (bf162*)(g_pool + oLo);
    float4 v = src[i];
    bf16 h0, l0, h1, l1, h2, l2, h3, l3;
    bsplit(v.x, h0, l0); bsplit(v.y, h1, l1);
    bsplit(v.z, h2, l2); bsplit(v.w, h3, l3);
    hi[i * 2 + 0] = __halves2bfloat162(h0, h1);
    hi[i * 2 + 1] = __halves2bfloat162(h2, h3);
    lo[i * 2 + 0] = __halves2bfloat162(l0, l1);
    lo[i * 2 + 1] = __halves2bfloat162(l2, l3);
}

// hi-only variant (for x: the lo plane is unused by the 2-product dual GEMM)
__global__ __launch_bounds__(256)
void ksplit_hi(const float4* __restrict__ src, size_t oHi, int n4)
{
    int i = blockIdx.x * 256 + threadIdx.x;
    if (i >= n4) return;
    bf162* hi = (bf162*)(g_pool + oHi);
    float4 v = src[i];
    hi[i * 2 + 0] = __halves2bfloat162(__float2bfloat16(v.x), __float2bfloat16(v.y));
    hi[i * 2 + 1] = __halves2bfloat162(__float2bfloat16(v.z), __float2bfloat16(v.w));
}

// ---------------- shared tile geometry ---------------------------------------
#define SROW  80            // smem bytes per 32-bf16 row (64B data + 16B pad)
#define TILEB (128 * SROW)  // 10240

enum { EPI_NONE = 0, EPI_SIGC = 1, EPI_SIGR = 3 };
enum { OUT_F32 = 0, OUT_SPLIT = 1, OUT_HI = 2 };

// ---------------- generalized bf16 mma GEMM ----------------------------------
// C[M,N] = epi( A @ B^T ). NPA/NPB = number of bf16 planes for A/B.
// Products: Ah*Bh (+ Ah*Bl if NPB==2) (+ Al*Bh if NPA==2)   [lo*lo dropped]
#define STAGEB (4 * TILEB)
#define GSMEM (2 * STAGEB)  // 81920

template<int EPI, int OUT, int NPA, int NPB>
__global__ __launch_bounds__(256, 2)
void mma_gemm(size_t oAh, size_t oAl, size_t oBh, size_t oBl,
              size_t oCf, size_t oCh, size_t oCl,
              int M, int N, int K,
              const float* __restrict__ bias)
{
    const bf16* Ah = (const bf16*)(g_pool + oAh);
    const bf16* Al = (const bf16*)(g_pool + oAl);
    const bf16* Bh = (const bf16*)(g_pool + oBh);
    const bf16* Bl = (const bf16*)(g_pool + oBl);
    float* Cf = (float*)(g_pool + oCf);
    bf16* Ch  = (bf16*)(g_pool + oCh);
    bf16* Cl  = (bf16*)(g_pool + oCl);

    extern __shared__ char smem[];
    const uint32_t sb = smem_u32(smem);
    const int tid  = threadIdx.x;
    const int lane = tid & 31;
    const int wid  = tid >> 5;
    const int wm   = wid & 3;
    const int wn   = wid >> 2;
    const int m0 = blockIdx.y * 128;
    const int n0 = blockIdx.x * 128;

    const int lr = tid >> 1;
    const int lh = tid & 1;
    const bf16* gAh = Ah + (size_t)(m0 + lr) * K + lh * 16;
    const bf16* gAl = Al + (size_t)(m0 + lr) * K + lh * 16;
    const bf16* gBh = Bh + (size_t)(n0 + lr) * K + lh * 16;
    const bf16* gBl = Bl + (size_t)(n0 + lr) * K + lh * 16;
    const uint32_t sdst = (uint32_t)(lr * SROW + lh * 32);

    const int NCH = K / 32;
    float c[2][8][4] = {};

    {
        uint32_t d = sb + sdst;
        cp32(d,             gAh);
        if (NPA == 2) cp32(d + TILEB, gAl);
        cp32(d + 2 * TILEB, gBh);
        if (NPB == 2) cp32(d + 3 * TILEB, gBl);
        CP_COMMIT();
        CP_WAIT0();
        __syncthreads();
    }

    for (int ch = 0; ch < NCH; ch++) {
        if (ch + 1 < NCH) {
            const int k0 = (ch + 1) * 32;
            uint32_t d = sb + ((ch + 1) & 1) * STAGEB + sdst;
            cp32(d,             gAh + k0);
            if (NPA == 2) cp32(d + TILEB, gAl + k0);
            cp32(d + 2 * TILEB, gBh + k0);
            if (NPB == 2) cp32(d + 3 * TILEB, gBl + k0);
            CP_COMMIT();
        }

        const uint32_t base = sb + (ch & 1) * STAGEB;
        #pragma unroll
        for (int ks = 0; ks < 2; ks++) {
            uint32_t ah[2][4], al[2][4];
            #pragma unroll
            for (int mf = 0; mf < 2; mf++) {
                uint32_t addr = base
                    + (uint32_t)((wm * 32 + mf * 16 + (lane & 15)) * SROW)
                    + (uint32_t)(ks * 32 + (lane >> 4) * 16);
                LDSM4(ah[mf][0], ah[mf][1], ah[mf][2], ah[mf][3], addr);
                if (NPA == 2)
                    LDSM4(al[mf][0], al[mf][1], al[mf][2], al[mf][3], addr + TILEB);
            }
            const int g = lane >> 3;
            #pragma unroll
            for (int p = 0; p < 4; p++) {
                uint32_t addr = base + 2 * TILEB
                    + (uint32_t)((wn * 64 + p * 16 + ((g & 2) ? 8 : 0) + (lane & 7)) * SROW)
                    + (uint32_t)(ks * 32 + (g & 1) * 16);
                uint32_t h0, h1, h2, h3;
                LDSM4(h0, h1, h2, h3, addr);
                uint32_t l0, l1, l2, l3;
                if (NPB == 2) LDSM4(l0, l1, l2, l3, addr + TILEB);
                #pragma unroll
                for (int mf = 0; mf < 2; mf++) {
                    MMA_BF16(c[mf][2*p],   ah[mf], h0, h1);
                    MMA_BF16(c[mf][2*p+1], ah[mf], h2, h3);
                    if (NPB == 2) {
                        MMA_BF16(c[mf][2*p],   ah[mf], l0, l1);
                        MMA_BF16(c[mf][2*p+1], ah[mf], l2, l3);
                    }
                    if (NPA == 2) {
                        MMA_BF16(c[mf][2*p],   al[mf], h0, h1);
                        MMA_BF16(c[mf][2*p+1], al[mf], h2, h3);
                    }
                }
            }
        }
        if (ch + 1 < NCH) CP_WAIT0();
        __syncthreads();
    }

    const int quad = lane >> 2;
    const int tq   = lane & 3;
    #pragma unroll
    for (int mf = 0; mf < 2; mf++) {
        const int r0 = m0 + wm * 32 + mf * 16 + quad;
        const int r1 = r0 + 8;
        float rb0 = 0.f, rb1 = 0.f;
        if (EPI == EPI_SIGR) { rb0 = bias[r0]; rb1 = bias[r1]; }
        #pragma unroll
        for (int nf = 0; nf < 8; nf++) {
            const int col = n0 + wn * 64 + nf * 8 + tq * 2;
            float v0 = c[mf][nf][0], v1 = c[mf][nf][1];
            float v2 = c[mf][nf][2], v3 = c[mf][nf][3];
            if (EPI == EPI_SIGC) {
                float2 bb = *(const float2*)(bias + col);
                v0 = sigmoidf_(v0 + bb.x); v1 = sigmoidf_(v1 + bb.y);
                v2 = sigmoidf_(v2 + bb.x); v3 = sigmoidf_(v3 + bb.y);
            } else if (EPI == EPI_SIGR) {
                v0 = sigmoidf_(v0 + rb0); v1 = sigmoidf_(v1 + rb0);
                v2 = sigmoidf_(v2 + rb1); v3 = sigmoidf_(v3 + rb1);
            }
            if (OUT == OUT_SPLIT) {
                bf16 h0, l0, h1, l1;
                bsplit(v0, h0, l0); bsplit(v1, h1, l1);
                *(bf162*)(Ch + (size_t)r0 * N + col) = __halves2bfloat162(h0, h1);
                *(bf162*)(Cl + (size_t)r0 * N + col) = __halves2bfloat162(l0, l1);
                bsplit(v2, h0, l0); bsplit(v3, h1, l1);
                *(bf162*)(Ch + (size_t)r1 * N + col) = __halves2bfloat162(h0, h1);
                *(bf162*)(Cl + (size_t)r1 * N + col) = __halves2bfloat162(l0, l1);
            } else if (OUT == OUT_HI) {
                *(bf162*)(Ch + (size_t)r0 * N + col) =
                    __halves2bfloat162(__float2bfloat16(v0), __float2bfloat16(v1));
                *(bf162*)(Ch + (size_t)r1 * N + col) =
                    __halves2bfloat162(__float2bfloat16(v2), __float2bfloat16(v3));
            } else {
                *(float2*)(Cf + (size_t)r0 * N + col) = make_float2(v0, v1);
                *(float2*)(Cf + (size_t)r1 * N + col) = make_float2(v2, v3);
            }
        }
    }
}

// ---------------- fused dual GEMM: it + ia' from shared A (2-product) --------
// 512 threads. Warps 0-7 -> it = sigmoid(x@Wi^T+bi) (fp32 out).
// Warps 8-15 -> ia' = sigmoid(x@Wia^T+bia)*ctx (split out, needed by G5).
// A = x_hi only (2-product: x_hi*W_hi + x_hi*W_lo; drops x_lo*W_hi).
// smem/stage: [Ah, B0h, B0l, B1h, B1l] x TILEB; 2 stages.
#define DSTAGEB (5 * TILEB)       // 51200
#define DGSMEM  (2 * DSTAGEB)     // 102400

__global__ __launch_bounds__(512, 1)
void mma_gemm_dual(const float* __restrict__ bias_i,
                   const float* __restrict__ bias_ia,
                   const float* __restrict__ ctx)
{
    extern __shared__ char smem[];
    const uint32_t sb = smem_u32(smem);
    const int tid  = threadIdx.x;
    const int lane = tid & 31;
    const int wid  = tid >> 5;
    const int wg   = wid >> 3;        // 0: it, 1: ia
    const int wl   = wid & 7;
    const int wm   = wl & 3;
    const int wn   = wl >> 2;
    const int m0 = blockIdx.y * 128;
    const int n0 = blockIdx.x * 128;
    const int K = HH;

    // loader: 5 tiles x 512 16B-chunks; each thread does 5 cp16 per stage
    const bf16* srcp[5];
    uint32_t dstp[5];
    {
        const bf16* baseA_h = (const bf16*)(g_pool + OFF_XH);
        const bf16* baseB0h = (const bf16*)(g_pool + OFF_WIH);
        const bf16* baseB0l = (const bf16*)(g_pool + OFF_WIL);
        const bf16* baseB1h = (const bf16*)(g_pool + OFF_WIAH);
        const bf16* baseB1l = (const bf16*)(g_pool + OFF_WIAL);
        #pragma unroll
        for (int t = 0; t < 5; t++) {
            int chunk = tid + t * 512;
            int tile = chunk >> 9;          // 0..4
            int pos  = chunk & 511;
            int row  = pos >> 2;
            int q    = pos & 3;
            const bf16* bp;
            int rbase;
            switch (tile) {
                case 0: bp = baseA_h; rbase = m0; break;
                case 1: bp = baseB0h; rbase = n0; break;
                case 2: bp = baseB0l; rbase = n0; break;
                case 3: bp = baseB1h; rbase = n0; break;
                default: bp = baseB1l; rbase = n0; break;
            }
            srcp[t] = bp + (size_t)(rbase + row) * K + q * 8;
            dstp[t] = (uint32_t)(tile * TILEB + row * SROW + q * 16);
        }
    }

    const int NCH = K / 32;
    float c[2][8][4] = {};

    {
        #pragma unroll
        for (int t = 0; t < 5; t++)
            cp16(sb + dstp[t], srcp[t]);
        CP_COMMIT();
        CP_WAIT0();
        __syncthreads();
    }

    const uint32_t bofs = (uint32_t)((1 + 2 * wg) * TILEB);

    for (int ch = 0; ch < NCH; ch++) {
        if (ch + 1 < NCH) {
            const int k0 = (ch + 1) * 32;
            const uint32_t stg = sb + ((ch + 1) & 1) * DSTAGEB;
            #pragma unroll
            for (int t = 0; t < 5; t++)
                cp16(stg + dstp[t], srcp[t] + k0);
            CP_COMMIT();
        }

        const uint32_t base = sb + (ch & 1) * DSTAGEB;
        #pragma unroll
        for (int ks = 0; ks < 2; ks++) {
            uint32_t ah[2][4];
            #pragma unroll
            for (int mf = 0; mf < 2; mf++) {
                uint32_t addr = base
                    + (uint32_t)((wm * 32 + mf * 16 + (lane & 15)) * SROW)
                    + (uint32_t)(ks * 32 + (lane >> 4) * 16);
                LDSM4(ah[mf][0], ah[mf][1], ah[mf][2], ah[mf][3], addr);
            }
            const int g = lane >> 3;
            #pragma unroll
            for (int p = 0; p < 4; p++) {
                uint32_t addr = base + bofs
                    + (uint32_t)((wn * 64 + p * 16 + ((g & 2) ? 8 : 0) + (lane & 7)) * SROW)
                    + (uint32_t)(ks * 32 + (g & 1) * 16);
                uint32_t h0, h1, h2, h3, l0, l1, l2, l3;
                LDSM4(h0, h1, h2, h3, addr);
                LDSM4(l0, l1, l2, l3, addr + TILEB);
                #pragma unroll
                for (int mf = 0; mf < 2; mf++) {
                    MMA_BF16(c[mf][2*p],   ah[mf], h0, h1);
                    MMA_BF16(c[mf][2*p],   ah[mf], l0, l1);
                    MMA_BF16(c[mf][2*p+1], ah[mf], h2, h3);
                    MMA_BF16(c[mf][2*p+1], ah[mf], l2, l3);
                }
            }
        }
        if (ch + 1 < NCH) CP_WAIT0();
        __syncthreads();
    }

    const int quad = lane >> 2;
    const int tq   = lane & 3;
    if (wg == 0) {
        float* Cf = (float*)(g_pool + OFF_IT);
        #pragma unroll
        for (int mf = 0; mf < 2; mf++) {
            const int r0 = m0 + wm * 32 + mf * 16 + quad;
            const int r1 = r0 + 8;
            #pragma unroll
            for (int nf = 0; nf < 8; nf++) {
                const int col = n0 + wn * 64 + nf * 8 + tq * 2;
                float2 bb = *(const float2*)(bias_i + col);
                float v0 = sigmoidf_(c[mf][nf][0] + bb.x);
                float v1 = sigmoidf_(c[mf][nf][1] + bb.y);
                float v2 = sigmoidf_(c[mf][nf][2] + bb.x);
                float v3 = sigmoidf_(c[mf][nf][3] + bb.y);
                *(float2*)(Cf + (size_t)r0 * CC + col) = make_float2(v0, v1);
                *(float2*)(Cf + (size_t)r1 * CC + col) = make_float2(v2, v3);
            }
        }
    } else {
        bf16* Ch = (bf16*)(g_pool + OFF_IAH);
        bf16* Cl = (bf16*)(g_pool + OFF_IAL);
        #pragma unroll
        for (int mf = 0; mf < 2; mf++) {
            const int r0 = m0 + wm * 32 + mf * 16 + quad;
            const int r1 = r0 + 8;
            #pragma unroll
            for (int nf = 0; nf < 8; nf++) {
                const int col = n0 + wn * 64 + nf * 8 + tq * 2;
                float2 bb = *(const float2*)(bias_ia + col);
                float2 ss = *(const float2*)(ctx + col);
                float v0 = sigmoidf_(c[mf][nf][0] + bb.x) * ss.x;
                float v1 = sigmoidf_(c[mf][nf][1] + bb.y) * ss.y;
                float v2 = sigmoidf_(c[mf][nf][2] + bb.x) * ss.x;
                float v3 = sigmoidf_(c[mf][nf][3] + bb.y) * ss.y;
                bf16 h0, l0, h1, l1;
                bsplit(v0, h0, l0); bsplit(v1, h1, l1);
                *(bf162*)(Ch + (size_t)r0 * CC + col) = __halves2bfloat162(h0, h1);
                *(bf162*)(Cl + (size_t)r0 * CC + col) = __halves2bfloat162(l0, l1);
                bsplit(v2, h0, l0); bsplit(v3, h1, l1);
                *(bf162*)(Ch + (size_t)r1 * CC + col) = __halves2bfloat162(h0, h1);
                *(bf162*)(Cl + (size_t)r1 * CC + col) = __halves2bfloat162(l0, l1);
            }
        }
    }
}

// ---------------- softmax over L=256; writes bf16 attn (hi only) -------------
__global__ __launch_bounds__(256)
void softmax256()
{
    const float* logits = (const float*)(g_pool + OFF_LOGITS);
    bf16* atth = (bf16*)(g_pool + OFF_ATTH);

    const int row = blockIdx.x * 8 + threadIdx.y;
    const int lane = threadIdx.x;
    const float* r = logits + (size_t)row * LL;

    float v[8];
    float mx = -1e30f;
    #pragma unroll
    for (int j = 0; j < 8; j++) {
        v[j] = r[lane + 32 * j];
        mx = fmaxf(mx, v[j]);
    }
    #pragma unroll
    for (int s = 16; s > 0; s >>= 1)
        mx = fmaxf(mx, __shfl_xor_sync(0xffffffff, mx, s));

    float sum = 0.0f;
    #pragma unroll
    for (int j = 0; j < 8; j++) {
        v[j] = __expf(v[j] - mx);
        sum += v[j];
    }
    #pragma unroll
    for (int s = 16; s > 0; s >>= 1)
        sum += __shfl_xor_sync(0xffffffff, sum, s);

    const float inv = 1.0f / sum;
    const size_t ro = (size_t)row * LL;
    #pragma unroll
    for (int j = 0; j < 8; j++)
        atth[ro + lane + 32 * j] = __float2bfloat16(v[j] * inv);
}

// ---------------- fusion: sum_s it[b,s,c] * w[b,s,c] ------------------------
__global__ __launch_bounds__(512)
void fusion_partial()
{
    const float* it = (const float*)(g_pool + OFF_IT);
    const float* w  = (const float*)(g_pool + OFF_W);
    float* fp = (float*)(g_pool + OFF_FP);

    const int b = blockIdx.x, ns = blockIdx.y, cidx = threadIdx.x;
    size_t base = ((size_t)b * SS + (size_t)ns * 64) * CC + cidx;
    float acc = 0.0f;
    #pragma unroll 4
    for (int s = 0; s < 64; s++)
        acc += it[base + (size_t)s * CC] * w[base + (size_t)s * CC];
    fp[((size_t)b * 32 + ns) * CC + cidx] = acc;
}

__global__ __launch_bounds__(512)
void fusion_reduce()
{
    const float* fp = (const float*)(g_pool + OFF_FP);
    float* fu = (float*)(g_pool + OFF_FU);
    const int b = blockIdx.x, cidx = threadIdx.x;
    float acc = 0.0f;
    #pragma unroll
    for (int ns = 0; ns < 32; ns++)
        acc += fp[((size_t)b * 32 + ns) * CC + cidx];
    fu[(size_t)b * CC + cidx] = acc;
}

// ---------------- final: out[b,h] = sum_c fusion[b,c] * Wp[h,c] -------------
__global__ __launch_bounds__(256)
void final_gemm(const float* __restrict__ Wp, float* __restrict__ out)
{
    __shared__ float fs[CC];
    const float* fu = (const float*)(g_pool + OFF_FU);
    const int b = blockIdx.x;
    const int h = blockIdx.y * 256 + threadIdx.x;

    for (int i = threadIdx.x; i < CC; i += 256)
        fs[i] = fu[(size_t)b * CC + i];
    __syncthreads();

    float acc = 0.0f;
    const float4* wp4 = (const float4*)(Wp + (size_t)h * CC);
    const float4* fs4 = (const float4*)fs;
    #pragma unroll 4
    for (int c4 = 0; c4 < CC / 4; c4++) {
        float4 w = wp4[c4], f = fs4[c4];
        acc += w.x * f.x + w.y * f.y + w.z * f.z + w.w * f.w;
    }
    out[(size_t)b * HH + h] = acc;
}

// ---------------- launch ----------------------------------------------------
extern "C" void kernel_launch(void* const* d_in, const int* in_sizes, int n_in,
                              void* d_out, int out_size)
{
    const float* x   = (const float*)d_in[0];
    const float* lab = (const float*)d_in[1];
    const float* Wi  = (const float*)d_in[2];
    const float* bi  = (const float*)d_in[3];
    const float* Wl  = (const float*)d_in[4];
    const float* bl  = (const float*)d_in[5];
    const float* Wia = (const float*)d_in[6];
    const float* bia = (const float*)d_in[7];
    const float* Wla = (const float*)d_in[8];
    const float* bla = (const float*)d_in[9];
    const float* ctx = (const float*)d_in[10];
    const float* Wp  = (const float*)d_in[11];
    float* out = (float*)d_out;

    cudaFuncSetAttribute(mma_gemm<EPI_SIGR, OUT_HI, 2, 2>,    cudaFuncAttributeMaxDynamicSharedMemorySize, GSMEM);
    cudaFuncSetAttribute(mma_gemm<EPI_SIGC, OUT_SPLIT, 2, 2>, cudaFuncAttributeMaxDynamicSharedMemorySize, GSMEM);
    cudaFuncSetAttribute(mma_gemm<EPI_NONE, OUT_F32, 2, 2>,   cudaFuncAttributeMaxDynamicSharedMemorySize, GSMEM);
    cudaFuncSetAttribute(mma_gemm<EPI_NONE, OUT_F32, 1, 1>,   cudaFuncAttributeMaxDynamicSharedMemorySize, GSMEM);
    cudaFuncSetAttribute(mma_gemm_dual,                        cudaFuncAttributeMaxDynamicSharedMemorySize, DGSMEM);

    // ---- input splits ----
    ksplit_hi<<<(MROWS * HH / 4 + 255) / 256, 256>>>((const float4*)x, OFF_XH, MROWS * HH / 4);
    ksplit<<<(LL * HH / 4 + 255) / 256, 256>>>((const float4*)lab, OFF_LABH, OFF_LABL, LL * HH / 4);
    ksplit<<<(CC * HH / 4 + 255) / 256, 256>>>((const float4*)Wi,  OFF_WIH,  OFF_WIL,  CC * HH / 4);
    ksplit<<<(CC * HH / 4 + 255) / 256, 256>>>((const float4*)Wl,  OFF_WLH,  OFF_WLL,  CC * HH / 4);
    ksplit<<<(CC * HH / 4 + 255) / 256, 256>>>((const float4*)Wia, OFF_WIAH, OFF_WIAL, CC * HH / 4);
    ksplit<<<(CC * HH / 4 + 255) / 256, 256>>>((const float4*)Wla, OFF_WLAH, OFF_WLAL, CC * HH / 4);

    // ---- fused G3+G4 (2-product): it (fp32) and ia' (split) ----
    mma_gemm_dual<<<dim3(CC / 128, MROWS / 128), 512, DGSMEM>>>(bi, bia, ctx);

    // ---- G1: ltT[c,l] = sigmoid(Wl @ lab^T + bl[row]), hi-only out ----
    mma_gemm<EPI_SIGR, OUT_HI, 2, 2><<<dim3(LL / 128, CC / 128), 256, GSMEM>>>(
        OFF_WLH, OFF_WLL, OFF_LABH, OFF_LABL, 0, OFF_LTH, 0, CC, LL, HH, bl);

    // ---- G2: la[l,c] = sigmoid(lab @ Wla^T + bla[col]), split out ----
    mma_gemm<EPI_SIGC, OUT_SPLIT, 2, 2><<<dim3(CC / 128, LL / 128), 256, GSMEM>>>(
        OFF_LABH, OFF_LABL, OFF_WLAH, OFF_WLAL, 0, OFF_LAH, OFF_LAL, LL, CC, HH, bla);

    // ---- G5: logits = ia' @ la^T (3-product) ----
    mma_gemm<EPI_NONE, OUT_F32, 2, 2><<<dim3(LL / 128, MROWS / 128), 256, GSMEM>>>(
        OFF_IAH, OFF_IAL, OFF_LAH, OFF_LAL, OFF_LOGITS, 0, 0, MROWS, LL, CC, nullptr);

    // ---- softmax -> attn (bf16 hi) ----
    softmax256<<<MROWS / 8, dim3(32, 8)>>>();

    // ---- G7: weighted = attn @ ltT^T (1-product) ----
    mma_gemm<EPI_NONE, OUT_F32, 1, 1><<<dim3(CC / 128, MROWS / 128), 256, GSMEM>>>(
        OFF_ATTH, 0, OFF_LTH, 0, OFF_W, 0, 0, MROWS, CC, LL, nullptr);

    // ---- fusion + final projection ----
    fusion_partial<<<dim3(BB, 32), 512>>>();
    fusion_reduce<<<BB, 512>>>();
    final_gemm<<<dim3(BB, HH / 256), 256>>>(Wp, out);
}

// round 11
// speedup vs baseline: 1.3684x; 1.0884x over previous
#include <cuda_runtime.h>
#include <cuda_bf16.h>
#include <cstdint>
#include <cstddef>

// Problem dims (fixed)
#define BB 16
#define SS 2048
#define LL 256
#define HH 768
#define CC 512
#define MROWS (BB*SS)   // 32768

typedef __nv_bfloat16  bf16;
typedef __nv_bfloat162 bf162;

// ---------------- one static scratch pool, byte-addressed -------------------
constexpr size_t SZ_IT     = (size_t)MROWS * CC * 4;
constexpr size_t SZ_LOGITS = (size_t)MROWS * LL * 4;
constexpr size_t SZ_FP     = (size_t)256 * CC * 4;          // fpart[256 mblk][512]
constexpr size_t SZ_FU     = (size_t)BB * CC * 4;
constexpr size_t SZ_X2     = (size_t)MROWS * HH * 2;
constexpr size_t SZ_LAB2   = (size_t)LL * HH * 2;
constexpr size_t SZ_WT2    = (size_t)CC * HH * 2;
constexpr size_t SZ_IA2    = (size_t)MROWS * CC * 2;
constexpr size_t SZ_ATT2   = (size_t)MROWS * LL * 2;
constexpr size_t SZ_LC2    = (size_t)LL * CC * 2;

constexpr size_t OFF_IT     = 0;
constexpr size_t OFF_LOGITS = OFF_IT + SZ_IT;
constexpr size_t OFF_FP     = OFF_LOGITS + SZ_LOGITS;
constexpr size_t OFF_FU     = OFF_FP + SZ_FP;
constexpr size_t OFF_XH     = OFF_FU + SZ_FU;
constexpr size_t OFF_LABH   = OFF_XH + SZ_X2;
constexpr size_t OFF_LABL   = OFF_LABH + SZ_LAB2;
constexpr size_t OFF_WIH    = OFF_LABL + SZ_LAB2;
constexpr size_t OFF_WIL    = OFF_WIH + SZ_WT2;
constexpr size_t OFF_WLH    = OFF_WIL + SZ_WT2;
constexpr size_t OFF_WLL    = OFF_WLH + SZ_WT2;
constexpr size_t OFF_WIAH   = OFF_WLL + SZ_WT2;
constexpr size_t OFF_WIAL   = OFF_WIAH + SZ_WT2;
constexpr size_t OFF_WLAH   = OFF_WIAL + SZ_WT2;
constexpr size_t OFF_WLAL   = OFF_WLAH + SZ_WT2;
constexpr size_t OFF_IAH    = OFF_WLAL + SZ_WT2;
constexpr size_t OFF_ATTH   = OFF_IAH + SZ_IA2;
constexpr size_t OFF_LTH    = OFF_ATTH + SZ_ATT2;
constexpr size_t OFF_LAH    = OFF_LTH + SZ_LC2;
constexpr size_t OFF_LAL    = OFF_LAH + SZ_LC2;
constexpr size_t POOL_BYTES = OFF_LAL + SZ_LC2;

__device__ __align__(16) unsigned char g_pool[POOL_BYTES];

// ---------------- helpers ---------------------------------------------------
__device__ __forceinline__ uint32_t smem_u32(const void* p) {
    uint32_t a;
    asm("{ .reg .u64 t; cvta.to.shared.u64 t, %1; cvt.u32.u64 %0, t; }" : "=r"(a) : "l"(p));
    return a;
}
__device__ __forceinline__ void cp16(uint32_t dst, const void* src) {
    asm volatile("cp.async.cg.shared.global [%0], [%1], 16;" :: "r"(dst), "l"(src) : "memory");
}
__device__ __forceinline__ void cp32(uint32_t dst, const bf16* src) {
    cp16(dst, src);
    cp16(dst + 16, src + 8);
}
#define CP_COMMIT() asm volatile("cp.async.commit_group;" ::: "memory")
#define CP_WAIT0()  asm volatile("cp.async.wait_group 0;"  ::: "memory")

#define LDSM4(R0,R1,R2,R3,ADDR) \
    asm volatile("ldmatrix.sync.aligned.m8n8.x4.shared.b16 {%0,%1,%2,%3}, [%4];" \
                 : "=r"(R0),"=r"(R1),"=r"(R2),"=r"(R3) : "r"(ADDR))

#define MMA_BF16(C,A,B0,B1) \
    asm volatile("mma.sync.aligned.m16n8k16.row.col.f32.bf16.bf16.f32 " \
                 "{%0,%1,%2,%3},{%4,%5,%6,%7},{%8,%9},{%0,%1,%2,%3};" \
                 : "+f"((C)[0]),"+f"((C)[1]),"+f"((C)[2]),"+f"((C)[3]) \
                 : "r"((A)[0]),"r"((A)[1]),"r"((A)[2]),"r"((A)[3]), \
                   "r"(B0),"r"(B1))

__device__ __forceinline__ void bsplit(float v, bf16& h, bf16& l) {
    h = __float2bfloat16(v);
    l = __float2bfloat16(v - __bfloat162float(h));
}
__device__ __forceinline__ float sigmoidf_(float v) {
    return 1.0f / (1.0f + __expf(-v));
}

// ---------------- fp32 -> bf16 splits ----------------------------------------
__global__ __launch_bounds__(256)
void ksplit(const float4* __restrict__ src, size_t oHi, size_t oLo, int n4)
{
    int i = blockIdx.x * 256 + threadIdx.x;
    if (i >= n4) return;
    bf162* hi = (bf162*)(g_pool + oHi);
    bf162* lo = (bf162*)(g_pool + oLo);
    float4 v = src[i];
    bf16 h0, l0, h1, l1, h2, l2, h3, l3;
    bsplit(v.x, h0, l0); bsplit(v.y, h1, l1);
    bsplit(v.z, h2, l2); bsplit(v.w, h3, l3);
    hi[i * 2 + 0] = __halves2bfloat162(h0, h1);
    hi[i * 2 + 1] = __halves2bfloat162(h2, h3);
    lo[i * 2 + 0] = __halves2bfloat162(l0, l1);
    lo[i * 2 + 1] = __halves2bfloat162(l2, l3);
}

__global__ __launch_bounds__(256)
void ksplit_hi(const float4* __restrict__ src, size_t oHi, int n4)
{
    int i = blockIdx.x * 256 + threadIdx.x;
    if (i >= n4) return;
    bf162* hi = (bf162*)(g_pool + oHi);
    float4 v = src[i];
    hi[i * 2 + 0] = __halves2bfloat162(__float2bfloat16(v.x), __float2bfloat16(v.y));
    hi[i * 2 + 1] = __halves2bfloat162(__float2bfloat16(v.z), __float2bfloat16(v.w));
}

// ---------------- shared tile geometry ---------------------------------------
#define SROW  80            // smem bytes per 32-bf16 row (64B data + 16B pad)
#define TILEB (128 * SROW)  // 10240

enum { EPI_NONE = 0, EPI_SIGC = 1, EPI_SIGR = 3 };
enum { OUT_F32 = 0, OUT_SPLIT = 1, OUT_HI = 2 };

// ---------------- generalized bf16 mma GEMM ----------------------------------
// C[M,N] = epi( A @ B^T ). NPA/NPB = planes. Products: Ah*Bh (+Ah*Bl) (+Al*Bh)
#define STAGEB (4 * TILEB)
#define GSMEM (2 * STAGEB)  // 81920

template<int EPI, int OUT, int NPA, int NPB>
__global__ __launch_bounds__(256, 2)
void mma_gemm(size_t oAh, size_t oAl, size_t oBh, size_t oBl,
              size_t oCf, size_t oCh, size_t oCl,
              int M, int N, int K,
              const float* __restrict__ bias)
{
    const bf16* Ah = (const bf16*)(g_pool + oAh);
    const bf16* Al = (const bf16*)(g_pool + oAl);
    const bf16* Bh = (const bf16*)(g_pool + oBh);
    const bf16* Bl = (const bf16*)(g_pool + oBl);
    float* Cf = (float*)(g_pool + oCf);
    bf16* Ch  = (bf16*)(g_pool + oCh);
    bf16* Cl  = (bf16*)(g_pool + oCl);

    extern __shared__ char smem[];
    const uint32_t sb = smem_u32(smem);
    const int tid  = threadIdx.x;
    const int lane = tid & 31;
    const int wid  = tid >> 5;
    const int wm   = wid & 3;
    const int wn   = wid >> 2;
    const int m0 = blockIdx.y * 128;
    const int n0 = blockIdx.x * 128;

    const int lr = tid >> 1;
    const int lh = tid & 1;
    const bf16* gAh = Ah + (size_t)(m0 + lr) * K + lh * 16;
    const bf16* gAl = Al + (size_t)(m0 + lr) * K + lh * 16;
    const bf16* gBh = Bh + (size_t)(n0 + lr) * K + lh * 16;
    const bf16* gBl = Bl + (size_t)(n0 + lr) * K + lh * 16;
    const uint32_t sdst = (uint32_t)(lr * SROW + lh * 32);

    const int NCH = K / 32;
    float c[2][8][4] = {};

    {
        uint32_t d = sb + sdst;
        cp32(d,             gAh);
        if (NPA == 2) cp32(d + TILEB, gAl);
        cp32(d + 2 * TILEB, gBh);
        if (NPB == 2) cp32(d + 3 * TILEB, gBl);
        CP_COMMIT();
        CP_WAIT0();
        __syncthreads();
    }

    for (int ch = 0; ch < NCH; ch++) {
        if (ch + 1 < NCH) {
            const int k0 = (ch + 1) * 32;
            uint32_t d = sb + ((ch + 1) & 1) * STAGEB + sdst;
            cp32(d,             gAh + k0);
            if (NPA == 2) cp32(d + TILEB, gAl + k0);
            cp32(d + 2 * TILEB, gBh + k0);
            if (NPB == 2) cp32(d + 3 * TILEB, gBl + k0);
            CP_COMMIT();
        }

        const uint32_t base = sb + (ch & 1) * STAGEB;
        #pragma unroll
        for (int ks = 0; ks < 2; ks++) {
            uint32_t ah[2][4], al[2][4];
            #pragma unroll
            for (int mf = 0; mf < 2; mf++) {
                uint32_t addr = base
                    + (uint32_t)((wm * 32 + mf * 16 + (lane & 15)) * SROW)
                    + (uint32_t)(ks * 32 + (lane >> 4) * 16);
                LDSM4(ah[mf][0], ah[mf][1], ah[mf][2], ah[mf][3], addr);
                if (NPA == 2)
                    LDSM4(al[mf][0], al[mf][1], al[mf][2], al[mf][3], addr + TILEB);
            }
            const int g = lane >> 3;
            #pragma unroll
            for (int p = 0; p < 4; p++) {
                uint32_t addr = base + 2 * TILEB
                    + (uint32_t)((wn * 64 + p * 16 + ((g & 2) ? 8 : 0) + (lane & 7)) * SROW)
                    + (uint32_t)(ks * 32 + (g & 1) * 16);
                uint32_t h0, h1, h2, h3;
                LDSM4(h0, h1, h2, h3, addr);
                uint32_t l0, l1, l2, l3;
                if (NPB == 2) LDSM4(l0, l1, l2, l3, addr + TILEB);
                #pragma unroll
                for (int mf = 0; mf < 2; mf++) {
                    MMA_BF16(c[mf][2*p],   ah[mf], h0, h1);
                    MMA_BF16(c[mf][2*p+1], ah[mf], h2, h3);
                    if (NPB == 2) {
                        MMA_BF16(c[mf][2*p],   ah[mf], l0, l1);
                        MMA_BF16(c[mf][2*p+1], ah[mf], l2, l3);
                    }
                    if (NPA == 2) {
                        MMA_BF16(c[mf][2*p],   al[mf], h0, h1);
                        MMA_BF16(c[mf][2*p+1], al[mf], h2, h3);
                    }
                }
            }
        }
        if (ch + 1 < NCH) CP_WAIT0();
        __syncthreads();
    }

    const int quad = lane >> 2;
    const int tq   = lane & 3;
    #pragma unroll
    for (int mf = 0; mf < 2; mf++) {
        const int r0 = m0 + wm * 32 + mf * 16 + quad;
        const int r1 = r0 + 8;
        float rb0 = 0.f, rb1 = 0.f;
        if (EPI == EPI_SIGR) { rb0 = bias[r0]; rb1 = bias[r1]; }
        #pragma unroll
        for (int nf = 0; nf < 8; nf++) {
            const int col = n0 + wn * 64 + nf * 8 + tq * 2;
            float v0 = c[mf][nf][0], v1 = c[mf][nf][1];
            float v2 = c[mf][nf][2], v3 = c[mf][nf][3];
            if (EPI == EPI_SIGC) {
                float2 bb = *(const float2*)(bias + col);
                v0 = sigmoidf_(v0 + bb.x); v1 = sigmoidf_(v1 + bb.y);
                v2 = sigmoidf_(v2 + bb.x); v3 = sigmoidf_(v3 + bb.y);
            } else if (EPI == EPI_SIGR) {
                v0 = sigmoidf_(v0 + rb0); v1 = sigmoidf_(v1 + rb0);
                v2 = sigmoidf_(v2 + rb1); v3 = sigmoidf_(v3 + rb1);
            }
            if (OUT == OUT_SPLIT) {
                bf16 h0, l0, h1, l1;
                bsplit(v0, h0, l0); bsplit(v1, h1, l1);
                *(bf162*)(Ch + (size_t)r0 * N + col) = __halves2bfloat162(h0, h1);
                *(bf162*)(Cl + (size_t)r0 * N + col) = __halves2bfloat162(l0, l1);
                bsplit(v2, h0, l0); bsplit(v3, h1, l1);
                *(bf162*)(Ch + (size_t)r1 * N + col) = __halves2bfloat162(h0, h1);
                *(bf162*)(Cl + (size_t)r1 * N + col) = __halves2bfloat162(l0, l1);
            } else if (OUT == OUT_HI) {
                *(bf162*)(Ch + (size_t)r0 * N + col) =
                    __halves2bfloat162(__float2bfloat16(v0), __float2bfloat16(v1));
                *(bf162*)(Ch + (size_t)r1 * N + col) =
                    __halves2bfloat162(__float2bfloat16(v2), __float2bfloat16(v3));
            } else {
                *(float2*)(Cf + (size_t)r0 * N + col) = make_float2(v0, v1);
                *(float2*)(Cf + (size_t)r1 * N + col) = make_float2(v2, v3);
            }
        }
    }
}

// ---------------- fused dual GEMM: it + ia' from shared A (2-product) --------
// Warps 0-7 -> it fp32; warps 8-15 -> ia' bf16 hi only (G5 is now 2-product).
#define DSTAGEB (5 * TILEB)       // 51200
#define DGSMEM  (2 * DSTAGEB)     // 102400

__global__ __launch_bounds__(512, 1)
void mma_gemm_dual(const float* __restrict__ bias_i,
                   const float* __restrict__ bias_ia,
                   const float* __restrict__ ctx)
{
    extern __shared__ char smem[];
    const uint32_t sb = smem_u32(smem);
    const int tid  = threadIdx.x;
    const int lane = tid & 31;
    const int wid  = tid >> 5;
    const int wg   = wid >> 3;        // 0: it, 1: ia
    const int wl   = wid & 7;
    const int wm   = wl & 3;
    const int wn   = wl >> 2;
    const int m0 = blockIdx.y * 128;
    const int n0 = blockIdx.x * 128;
    const int K = HH;

    const bf16* srcp[5];
    uint32_t dstp[5];
    {
        const bf16* baseA_h = (const bf16*)(g_pool + OFF_XH);
        const bf16* baseB0h = (const bf16*)(g_pool + OFF_WIH);
        const bf16* baseB0l = (const bf16*)(g_pool + OFF_WIL);
        const bf16* baseB1h = (const bf16*)(g_pool + OFF_WIAH);
        const bf16* baseB1l = (const bf16*)(g_pool + OFF_WIAL);
        #pragma unroll
        for (int t = 0; t < 5; t++) {
            int chunk = tid + t * 512;
            int tile = chunk >> 9;
            int pos  = chunk & 511;
            int row  = pos >> 2;
            int q    = pos & 3;
            const bf16* bp;
            int rbase;
            switch (tile) {
                case 0: bp = baseA_h; rbase = m0; break;
                case 1: bp = baseB0h; rbase = n0; break;
                case 2: bp = baseB0l; rbase = n0; break;
                case 3: bp = baseB1h; rbase = n0; break;
                default: bp = baseB1l; rbase = n0; break;
            }
            srcp[t] = bp + (size_t)(rbase + row) * K + q * 8;
            dstp[t] = (uint32_t)(tile * TILEB + row * SROW + q * 16);
        }
    }

    const int NCH = K / 32;
    float c[2][8][4] = {};

    {
        #pragma unroll
        for (int t = 0; t < 5; t++)
            cp16(sb + dstp[t], srcp[t]);
        CP_COMMIT();
        CP_WAIT0();
        __syncthreads();
    }

    const uint32_t bofs = (uint32_t)((1 + 2 * wg) * TILEB);

    for (int ch = 0; ch < NCH; ch++) {
        if (ch + 1 < NCH) {
            const int k0 = (ch + 1) * 32;
            const uint32_t stg = sb + ((ch + 1) & 1) * DSTAGEB;
            #pragma unroll
            for (int t = 0; t < 5; t++)
                cp16(stg + dstp[t], srcp[t] + k0);
            CP_COMMIT();
        }

        const uint32_t base = sb + (ch & 1) * DSTAGEB;
        #pragma unroll
        for (int ks = 0; ks < 2; ks++) {
            uint32_t ah[2][4];
            #pragma unroll
            for (int mf = 0; mf < 2; mf++) {
                uint32_t addr = base
                    + (uint32_t)((wm * 32 + mf * 16 + (lane & 15)) * SROW)
                    + (uint32_t)(ks * 32 + (lane >> 4) * 16);
                LDSM4(ah[mf][0], ah[mf][1], ah[mf][2], ah[mf][3], addr);
            }
            const int g = lane >> 3;
            #pragma unroll
            for (int p = 0; p < 4; p++) {
                uint32_t addr = base + bofs
                    + (uint32_t)((wn * 64 + p * 16 + ((g & 2) ? 8 : 0) + (lane & 7)) * SROW)
                    + (uint32_t)(ks * 32 + (g & 1) * 16);
                uint32_t h0, h1, h2, h3, l0, l1, l2, l3;
                LDSM4(h0, h1, h2, h3, addr);
                LDSM4(l0, l1, l2, l3, addr + TILEB);
                #pragma unroll
                for (int mf = 0; mf < 2; mf++) {
                    MMA_BF16(c[mf][2*p],   ah[mf], h0, h1);
                    MMA_BF16(c[mf][2*p],   ah[mf], l0, l1);
                    MMA_BF16(c[mf][2*p+1], ah[mf], h2, h3);
                    MMA_BF16(c[mf][2*p+1], ah[mf], l2, l3);
                }
            }
        }
        if (ch + 1 < NCH) CP_WAIT0();
        __syncthreads();
    }

    const int quad = lane >> 2;
    const int tq   = lane & 3;
    if (wg == 0) {
        float* Cf = (float*)(g_pool + OFF_IT);
        #pragma unroll
        for (int mf = 0; mf < 2; mf++) {
            const int r0 = m0 + wm * 32 + mf * 16 + quad;
            const int r1 = r0 + 8;
            #pragma unroll
            for (int nf = 0; nf < 8; nf++) {
                const int col = n0 + wn * 64 + nf * 8 + tq * 2;
                float2 bb = *(const float2*)(bias_i + col);
                float v0 = sigmoidf_(c[mf][nf][0] + bb.x);
                float v1 = sigmoidf_(c[mf][nf][1] + bb.y);
                float v2 = sigmoidf_(c[mf][nf][2] + bb.x);
                float v3 = sigmoidf_(c[mf][nf][3] + bb.y);
                *(float2*)(Cf + (size_t)r0 * CC + col) = make_float2(v0, v1);
                *(float2*)(Cf + (size_t)r1 * CC + col) = make_float2(v2, v3);
            }
        }
    } else {
        bf16* Ch = (bf16*)(g_pool + OFF_IAH);
        #pragma unroll
        for (int mf = 0; mf < 2; mf++) {
            const int r0 = m0 + wm * 32 + mf * 16 + quad;
            const int r1 = r0 + 8;
            #pragma unroll
            for (int nf = 0; nf < 8; nf++) {
                const int col = n0 + wn * 64 + nf * 8 + tq * 2;
                float2 bb = *(const float2*)(bias_ia + col);
                float2 ss = *(const float2*)(ctx + col);
                float v0 = sigmoidf_(c[mf][nf][0] + bb.x) * ss.x;
                float v1 = sigmoidf_(c[mf][nf][1] + bb.y) * ss.y;
                float v2 = sigmoidf_(c[mf][nf][2] + bb.x) * ss.x;
                float v3 = sigmoidf_(c[mf][nf][3] + bb.y) * ss.y;
                *(bf162*)(Ch + (size_t)r0 * CC + col) =
                    __halves2bfloat162(__float2bfloat16(v0), __float2bfloat16(v1));
                *(bf162*)(Ch + (size_t)r1 * CC + col) =
                    __halves2bfloat162(__float2bfloat16(v2), __float2bfloat16(v3));
            }
        }
    }
}

// ---------------- G7 + fusion: fpart[mblk][c] = sum_rows it * (attn @ lt^T) --
// A = attn hi [MROWS, 256], B = lt hi [512, 256]. 1-product.
#define FSTAGE (2 * TILEB)                 // Ah + Bh
#define F7SMEM (2 * FSTAGE + 4 * 128 * 4)  // 40960 + 2048 = 43008

__global__ __launch_bounds__(256, 2)
void mma_gemm_fuse()
{
    const bf16* Ah = (const bf16*)(g_pool + OFF_ATTH);
    const bf16* Bh = (const bf16*)(g_pool + OFF_LTH);
    const float* itp = (const float*)(g_pool + OFF_IT);
    float* fpart = (float*)(g_pool + OFF_FP);

    extern __shared__ char smem[];
    const uint32_t sb = smem_u32(smem);
    float* facc = (float*)(smem + 2 * FSTAGE);
    const int tid  = threadIdx.x;
    const int lane = tid & 31;
    const int wid  = tid >> 5;
    const int wm   = wid & 3;
    const int wn   = wid >> 2;
    const int m0 = blockIdx.y * 128;
    const int n0 = blockIdx.x * 128;
    const int K = LL;  // 256

    const int lr = tid >> 1;
    const int lh = tid & 1;
    const bf16* gAh = Ah + (size_t)(m0 + lr) * K + lh * 16;
    const bf16* gBh = Bh + (size_t)(n0 + lr) * K + lh * 16;
    const uint32_t sdst = (uint32_t)(lr * SROW + lh * 32);

    const int NCH = K / 32;  // 8
    float c[2][8][4] = {};

    {
        uint32_t d = sb + sdst;
        cp32(d,         gAh);
        cp32(d + TILEB, gBh);
        CP_COMMIT();
        CP_WAIT0();
        __syncthreads();
    }

    for (int ch = 0; ch < NCH; ch++) {
        if (ch + 1 < NCH) {
            const int k0 = (ch + 1) * 32;
            uint32_t d = sb + ((ch + 1) & 1) * FSTAGE + sdst;
            cp32(d,         gAh + k0);
            cp32(d + TILEB, gBh + k0);
            CP_COMMIT();
        }

        const uint32_t base = sb + (ch & 1) * FSTAGE;
        #pragma unroll
        for (int ks = 0; ks < 2; ks++) {
            uint32_t ah[2][4];
            #pragma unroll
            for (int mf = 0; mf < 2; mf++) {
                uint32_t addr = base
                    + (uint32_t)((wm * 32 + mf * 16 + (lane & 15)) * SROW)
                    + (uint32_t)(ks * 32 + (lane >> 4) * 16);
                LDSM4(ah[mf][0], ah[mf][1], ah[mf][2], ah[mf][3], addr);
            }
            const int g = lane >> 3;
            #pragma unroll
            for (int p = 0; p < 4; p++) {
                uint32_t addr = base + TILEB
                    + (uint32_t)((wn * 64 + p * 16 + ((g & 2) ? 8 : 0) + (lane & 7)) * SROW)
                    + (uint32_t)(ks * 32 + (g & 1) * 16);
                uint32_t h0, h1, h2, h3;
                LDSM4(h0, h1, h2, h3, addr);
                #pragma unroll
                for (int mf = 0; mf < 2; mf++) {
                    MMA_BF16(c[mf][2*p],   ah[mf], h0, h1);
                    MMA_BF16(c[mf][2*p+1], ah[mf], h2, h3);
                }
            }
        }
        if (ch + 1 < NCH) CP_WAIT0();
        __syncthreads();
    }

    // fused epilogue: multiply by it, reduce over the CTA's 128 rows
    const int quad = lane >> 2;
    const int tq   = lane & 3;
    float pc[16];
    #pragma unroll
    for (int i = 0; i < 16; i++) pc[i] = 0.0f;
    #pragma unroll
    for (int mf = 0; mf < 2; mf++) {
        const int r0g = m0 + wm * 32 + mf * 16 + quad;
        const int r1g = r0g + 8;
        #pragma unroll
        for (int nf = 0; nf < 8; nf++) {
            const int colg = n0 + wn * 64 + nf * 8 + tq * 2;
            float2 i0 = *(const float2*)(itp + (size_t)r0g * CC + colg);
            float2 i1 = *(const float2*)(itp + (size_t)r1g * CC + colg);
            pc[2*nf]   += c[mf][nf][0] * i0.x + c[mf][nf][2] * i1.x;
            pc[2*nf+1] += c[mf][nf][1] * i0.y + c[mf][nf][3] * i1.y;
        }
    }
    #pragma unroll
    for (int off = 4; off <= 16; off <<= 1)
        #pragma unroll
        for (int i = 0; i < 16; i++)
            pc[i] += __shfl_xor_sync(0xffffffff, pc[i], off);
    if (quad == 0) {
        #pragma unroll
        for (int nf = 0; nf < 8; nf++) {
            const int col = wn * 64 + nf * 8 + tq * 2;
            facc[wm * 128 + col]     = pc[2*nf];
            facc[wm * 128 + col + 1] = pc[2*nf+1];
        }
    }
    __syncthreads();
    if (tid < 128) {
        float s = facc[tid] + facc[128 + tid] + facc[256 + tid] + facc[384 + tid];
        fpart[(size_t)blockIdx.y * CC + n0 + tid] = s;
    }
}

// ---------------- softmax over L=256; writes bf16 attn (hi only) -------------
__global__ __launch_bounds__(256)
void softmax256()
{
    const float* logits = (const float*)(g_pool + OFF_LOGITS);
    bf16* atth = (bf16*)(g_pool + OFF_ATTH);

    const int row = blockIdx.x * 8 + threadIdx.y;
    const int lane = threadIdx.x;
    const float* r = logits + (size_t)row * LL;

    float v[8];
    float mx = -1e30f;
    #pragma unroll
    for (int j = 0; j < 8; j++) {
        v[j] = r[lane + 32 * j];
        mx = fmaxf(mx, v[j]);
    }
    #pragma unroll
    for (int s = 16; s > 0; s >>= 1)
        mx = fmaxf(mx, __shfl_xor_sync(0xffffffff, mx, s));

    float sum = 0.0f;
    #pragma unroll
    for (int j = 0; j < 8; j++) {
        v[j] = __expf(v[j] - mx);
        sum += v[j];
    }
    #pragma unroll
    for (int s = 16; s > 0; s >>= 1)
        sum += __shfl_xor_sync(0xffffffff, sum, s);

    const float inv = 1.0f / sum;
    const size_t ro = (size_t)row * LL;
    #pragma unroll
    for (int j = 0; j < 8; j++)
        atth[ro + lane + 32 * j] = __float2bfloat16(v[j] * inv);
}

// ---------------- fusion reduce: 16 m-blocks per batch -----------------------
__global__ __launch_bounds__(512)
void fusion_reduce()
{
    const float* fp = (const float*)(g_pool + OFF_FP);
    float* fu = (float*)(g_pool + OFF_FU);
    const int b = blockIdx.x, cidx = threadIdx.x;
    float acc = 0.0f;
    #pragma unroll
    for (int k = 0; k < 16; k++)
        acc += fp[((size_t)b * 16 + k) * CC + cidx];
    fu[(size_t)b * CC + cidx] = acc;
}

// ---------------- final: out[b,h] = sum_c fusion[b,c] * Wp[h,c] -------------
__global__ __launch_bounds__(256)
void final_gemm(const float* __restrict__ Wp, float* __restrict__ out)
{
    __shared__ float fs[CC];
    const float* fu = (const float*)(g_pool + OFF_FU);
    const int b = blockIdx.x;
    const int h = blockIdx.y * 256 + threadIdx.x;

    for (int i = threadIdx.x; i < CC; i += 256)
        fs[i] = fu[(size_t)b * CC + i];
    __syncthreads();

    float acc = 0.0f;
    const float4* wp4 = (const float4*)(Wp + (size_t)h * CC);
    const float4* fs4 = (const float4*)fs;
    #pragma unroll 4
    for (int c4 = 0; c4 < CC / 4; c4++) {
        float4 w = wp4[c4], f = fs4[c4];
        acc += w.x * f.x + w.y * f.y + w.z * f.z + w.w * f.w;
    }
    out[(size_t)b * HH + h] = acc;
}

// ---------------- launch ----------------------------------------------------
extern "C" void kernel_launch(void* const* d_in, const int* in_sizes, int n_in,
                              void* d_out, int out_size)
{
    const float* x   = (const float*)d_in[0];
    const float* lab = (const float*)d_in[1];
    const float* Wi  = (const float*)d_in[2];
    const float* bi  = (const float*)d_in[3];
    const float* Wl  = (const float*)d_in[4];
    const float* bl  = (const float*)d_in[5];
    const float* Wia = (const float*)d_in[6];
    const float* bia = (const float*)d_in[7];
    const float* Wla = (const float*)d_in[8];
    const float* bla = (const float*)d_in[9];
    const float* ctx = (const float*)d_in[10];
    const float* Wp  = (const float*)d_in[11];
    float* out = (float*)d_out;

    cudaFuncSetAttribute(mma_gemm<EPI_SIGR, OUT_HI, 2, 2>,    cudaFuncAttributeMaxDynamicSharedMemorySize, GSMEM);
    cudaFuncSetAttribute(mma_gemm<EPI_SIGC, OUT_SPLIT, 2, 2>, cudaFuncAttributeMaxDynamicSharedMemorySize, GSMEM);
    cudaFuncSetAttribute(mma_gemm<EPI_NONE, OUT_F32, 1, 2>,   cudaFuncAttributeMaxDynamicSharedMemorySize, GSMEM);
    cudaFuncSetAttribute(mma_gemm_dual,                        cudaFuncAttributeMaxDynamicSharedMemorySize, DGSMEM);
    cudaFuncSetAttribute(mma_gemm_fuse,                        cudaFuncAttributeMaxDynamicSharedMemorySize, F7SMEM);

    // ---- input splits ----
    ksplit_hi<<<(MROWS * HH / 4 + 255) / 256, 256>>>((const float4*)x, OFF_XH, MROWS * HH / 4);
    ksplit<<<(LL * HH / 4 + 255) / 256, 256>>>((const float4*)lab, OFF_LABH, OFF_LABL, LL * HH / 4);
    ksplit<<<(CC * HH / 4 + 255) / 256, 256>>>((const float4*)Wi,  OFF_WIH,  OFF_WIL,  CC * HH / 4);
    ksplit<<<(CC * HH / 4 + 255) / 256, 256>>>((const float4*)Wl,  OFF_WLH,  OFF_WLL,  CC * HH / 4);
    ksplit<<<(CC * HH / 4 + 255) / 256, 256>>>((const float4*)Wia, OFF_WIAH, OFF_WIAL, CC * HH / 4);
    ksplit<<<(CC * HH / 4 + 255) / 256, 256>>>((const float4*)Wla, OFF_WLAH, OFF_WLAL, CC * HH / 4);

    // ---- fused G3+G4 (2-product): it (fp32) and ia' (bf16 hi) ----
    mma_gemm_dual<<<dim3(CC / 128, MROWS / 128), 512, DGSMEM>>>(bi, bia, ctx);

    // ---- G1: ltT[c,l] = sigmoid(Wl @ lab^T + bl[row]), hi-only out ----
    mma_gemm<EPI_SIGR, OUT_HI, 2, 2><<<dim3(LL / 128, CC / 128), 256, GSMEM>>>(
        OFF_WLH, OFF_WLL, OFF_LABH, OFF_LABL, 0, OFF_LTH, 0, CC, LL, HH, bl);

    // ---- G2: la[l,c] = sigmoid(lab @ Wla^T + bla[col]), split out ----
    mma_gemm<EPI_SIGC, OUT_SPLIT, 2, 2><<<dim3(CC / 128, LL / 128), 256, GSMEM>>>(
        OFF_LABH, OFF_LABL, OFF_WLAH, OFF_WLAL, 0, OFF_LAH, OFF_LAL, LL, CC, HH, bla);

    // ---- G5: logits = ia' @ la^T (2-product: iah*lah + iah*lal) ----
    mma_gemm<EPI_NONE, OUT_F32, 1, 2><<<dim3(LL / 128, MROWS / 128), 256, GSMEM>>>(
        OFF_IAH, 0, OFF_LAH, OFF_LAL, OFF_LOGITS, 0, 0, MROWS, LL, CC, nullptr);

    // ---- softmax -> attn (bf16 hi) ----
    softmax256<<<MROWS / 8, dim3(32, 8)>>>();

    // ---- G7 + fusion_partial fused ----
    mma_gemm_fuse<<<dim3(CC / 128, MROWS / 128), 256, F7SMEM>>>();

    // ---- fusion + final projection ----
    fusion_reduce<<<BB, 512>>>();
    final_gemm<<<dim3(BB, HH / 256), 256>>>(Wp, out);
}

// round 12
// speedup vs baseline: 1.7260x; 1.2613x over previous
#include <cuda_runtime.h>
#include <cuda_bf16.h>
#include <cstdint>
#include <cstddef>

// Problem dims (fixed)
#define BB 16
#define SS 2048
#define LL 256
#define HH 768
#define CC 512
#define MROWS (BB*SS)   // 32768

typedef __nv_bfloat16  bf16;
typedef __nv_bfloat162 bf162;

// ---------------- one static scratch pool, byte-addressed -------------------
constexpr size_t SZ_IT     = (size_t)MROWS * CC * 4;
constexpr size_t SZ_LOGITS = (size_t)MROWS * LL * 4;
constexpr size_t SZ_FP     = (size_t)256 * CC * 4;
constexpr size_t SZ_FU     = (size_t)BB * CC * 4;
constexpr size_t SZ_X2     = (size_t)MROWS * HH * 2;
constexpr size_t SZ_LAB2   = (size_t)LL * HH * 2;
constexpr size_t SZ_WT2    = (size_t)CC * HH * 2;
constexpr size_t SZ_IA2    = (size_t)MROWS * CC * 2;
constexpr size_t SZ_ATT2   = (size_t)MROWS * LL * 2;
constexpr size_t SZ_LC2    = (size_t)LL * CC * 2;

constexpr size_t OFF_IT     = 0;
constexpr size_t OFF_LOGITS = OFF_IT + SZ_IT;
constexpr size_t OFF_FP     = OFF_LOGITS + SZ_LOGITS;
constexpr size_t OFF_FU     = OFF_FP + SZ_FP;
constexpr size_t OFF_XH     = OFF_FU + SZ_FU;
constexpr size_t OFF_LABH   = OFF_XH + SZ_X2;
constexpr size_t OFF_LABL   = OFF_LABH + SZ_LAB2;
constexpr size_t OFF_WIH    = OFF_LABL + SZ_LAB2;
constexpr size_t OFF_WLH    = OFF_WIH + SZ_WT2;
constexpr size_t OFF_WLL    = OFF_WLH + SZ_WT2;
constexpr size_t OFF_WIAH   = OFF_WLL + SZ_WT2;
constexpr size_t OFF_WLAH   = OFF_WIAH + SZ_WT2;
constexpr size_t OFF_WLAL   = OFF_WLAH + SZ_WT2;
constexpr size_t OFF_IAH    = OFF_WLAL + SZ_WT2;
constexpr size_t OFF_ATTH   = OFF_IAH + SZ_IA2;
constexpr size_t OFF_LTH    = OFF_ATTH + SZ_ATT2;
constexpr size_t OFF_LAH    = OFF_LTH + SZ_LC2;
constexpr size_t OFF_LAL    = OFF_LAH + SZ_LC2;
constexpr size_t POOL_BYTES = OFF_LAL + SZ_LC2;

__device__ __align__(16) unsigned char g_pool[POOL_BYTES];

// ---------------- helpers ---------------------------------------------------
__device__ __forceinline__ uint32_t smem_u32(const void* p) {
    uint32_t a;
    asm("{ .reg .u64 t; cvta.to.shared.u64 t, %1; cvt.u32.u64 %0, t; }" : "=r"(a) : "l"(p));
    return a;
}
__device__ __forceinline__ void cp16(uint32_t dst, const void* src) {
    asm volatile("cp.async.cg.shared.global [%0], [%1], 16;" :: "r"(dst), "l"(src) : "memory");
}
__device__ __forceinline__ void cp32(uint32_t dst, const bf16* src) {
    cp16(dst, src);
    cp16(dst + 16, src + 8);
}
#define CP_COMMIT() asm volatile("cp.async.commit_group;" ::: "memory")
#define CP_WAIT0()  asm volatile("cp.async.wait_group 0;"  ::: "memory")

#define LDSM4(R0,R1,R2,R3,ADDR) \
    asm volatile("ldmatrix.sync.aligned.m8n8.x4.shared.b16 {%0,%1,%2,%3}, [%4];" \
                 : "=r"(R0),"=r"(R1),"=r"(R2),"=r"(R3) : "r"(ADDR))

#define MMA_BF16(C,A,B0,B1) \
    asm volatile("mma.sync.aligned.m16n8k16.row.col.f32.bf16.bf16.f32 " \
                 "{%0,%1,%2,%3},{%4,%5,%6,%7},{%8,%9},{%0,%1,%2,%3};" \
                 : "+f"((C)[0]),"+f"((C)[1]),"+f"((C)[2]),"+f"((C)[3]) \
                 : "r"((A)[0]),"r"((A)[1]),"r"((A)[2]),"r"((A)[3]), \
                   "r"(B0),"r"(B1))

__device__ __forceinline__ void bsplit(float v, bf16& h, bf16& l) {
    h = __float2bfloat16(v);
    l = __float2bfloat16(v - __bfloat162float(h));
}
__device__ __forceinline__ float sigmoidf_(float v) {
    return 1.0f / (1.0f + __expf(-v));
}

// ---------------- fp32 -> bf16 splits ----------------------------------------
__global__ __launch_bounds__(256)
void ksplit(const float4* __restrict__ src, size_t oHi, size_t oLo, int n4)
{
    int i = blockIdx.x * 256 + threadIdx.x;
    if (i >= n4) return;
    bf162* hi = (bf162*)(g_pool + oHi);
    bf162* lo = (bf162*)(g_pool + oLo);
    float4 v = src[i];
    bf16 h0, l0, h1, l1, h2, l2, h3, l3;
    bsplit(v.x, h0, l0); bsplit(v.y, h1, l1);
    bsplit(v.z, h2, l2); bsplit(v.w, h3, l3);
    hi[i * 2 + 0] = __halves2bfloat162(h0, h1);
    hi[i * 2 + 1] = __halves2bfloat162(h2, h3);
    lo[i * 2 + 0] = __halves2bfloat162(l0, l1);
    lo[i * 2 + 1] = __halves2bfloat162(l2, l3);
}

__global__ __launch_bounds__(256)
void ksplit_hi(const float4* __restrict__ src, size_t oHi, int n4)
{
    int i = blockIdx.x * 256 + threadIdx.x;
    if (i >= n4) return;
    bf162* hi = (bf162*)(g_pool + oHi);
    float4 v = src[i];
    hi[i * 2 + 0] = __halves2bfloat162(__float2bfloat16(v.x), __float2bfloat16(v.y));
    hi[i * 2 + 1] = __halves2bfloat162(__float2bfloat16(v.z), __float2bfloat16(v.w));
}

// ---------------- shared tile geometry ---------------------------------------
#define SROW  80            // smem bytes per 32-bf16 row (64B data + 16B pad)
#define TILEB (128 * SROW)  // 10240

enum { EPI_NONE = 0, EPI_SIGC = 1, EPI_SIGR = 3 };
enum { OUT_F32 = 0, OUT_SPLIT = 1, OUT_HI = 2 };

// ---------------- generalized bf16 mma GEMM ----------------------------------
// C[M,N] = epi( A @ B^T ). NPA/NPB = planes. Products: Ah*Bh (+Ah*Bl) (+Al*Bh)
#define STAGEB (4 * TILEB)
#define GSMEM (2 * STAGEB)  // 81920

template<int EPI, int OUT, int NPA, int NPB>
__global__ __launch_bounds__(256, 2)
void mma_gemm(size_t oAh, size_t oAl, size_t oBh, size_t oBl,
              size_t oCf, size_t oCh, size_t oCl,
              int M, int N, int K,
              const float* __restrict__ bias)
{
    const bf16* Ah = (const bf16*)(g_pool + oAh);
    const bf16* Al = (const bf16*)(g_pool + oAl);
    const bf16* Bh = (const bf16*)(g_pool + oBh);
    const bf16* Bl = (const bf16*)(g_pool + oBl);
    float* Cf = (float*)(g_pool + oCf);
    bf16* Ch  = (bf16*)(g_pool + oCh);
    bf16* Cl  = (bf16*)(g_pool + oCl);

    extern __shared__ char smem[];
    const uint32_t sb = smem_u32(smem);
    const int tid  = threadIdx.x;
    const int lane = tid & 31;
    const int wid  = tid >> 5;
    const int wm   = wid & 3;
    const int wn   = wid >> 2;
    const int m0 = blockIdx.y * 128;
    const int n0 = blockIdx.x * 128;

    const int lr = tid >> 1;
    const int lh = tid & 1;
    const bf16* gAh = Ah + (size_t)(m0 + lr) * K + lh * 16;
    const bf16* gAl = Al + (size_t)(m0 + lr) * K + lh * 16;
    const bf16* gBh = Bh + (size_t)(n0 + lr) * K + lh * 16;
    const bf16* gBl = Bl + (size_t)(n0 + lr) * K + lh * 16;
    const uint32_t sdst = (uint32_t)(lr * SROW + lh * 32);

    const int NCH = K / 32;
    float c[2][8][4] = {};

    {
        uint32_t d = sb + sdst;
        cp32(d,             gAh);
        if (NPA == 2) cp32(d + TILEB, gAl);
        cp32(d + 2 * TILEB, gBh);
        if (NPB == 2) cp32(d + 3 * TILEB, gBl);
        CP_COMMIT();
        CP_WAIT0();
        __syncthreads();
    }

    for (int ch = 0; ch < NCH; ch++) {
        if (ch + 1 < NCH) {
            const int k0 = (ch + 1) * 32;
            uint32_t d = sb + ((ch + 1) & 1) * STAGEB + sdst;
            cp32(d,             gAh + k0);
            if (NPA == 2) cp32(d + TILEB, gAl + k0);
            cp32(d + 2 * TILEB, gBh + k0);
            if (NPB == 2) cp32(d + 3 * TILEB, gBl + k0);
            CP_COMMIT();
        }

        const uint32_t base = sb + (ch & 1) * STAGEB;
        #pragma unroll
        for (int ks = 0; ks < 2; ks++) {
            uint32_t ah[2][4], al[2][4];
            #pragma unroll
            for (int mf = 0; mf < 2; mf++) {
                uint32_t addr = base
                    + (uint32_t)((wm * 32 + mf * 16 + (lane & 15)) * SROW)
                    + (uint32_t)(ks * 32 + (lane >> 4) * 16);
                LDSM4(ah[mf][0], ah[mf][1], ah[mf][2], ah[mf][3], addr);
                if (NPA == 2)
                    LDSM4(al[mf][0], al[mf][1], al[mf][2], al[mf][3], addr + TILEB);
            }
            const int g = lane >> 3;
            #pragma unroll
            for (int p = 0; p < 4; p++) {
                uint32_t addr = base + 2 * TILEB
                    + (uint32_t)((wn * 64 + p * 16 + ((g & 2) ? 8 : 0) + (lane & 7)) * SROW)
                    + (uint32_t)(ks * 32 + (g & 1) * 16);
                uint32_t h0, h1, h2, h3;
                LDSM4(h0, h1, h2, h3, addr);
                uint32_t l0, l1, l2, l3;
                if (NPB == 2) LDSM4(l0, l1, l2, l3, addr + TILEB);
                #pragma unroll
                for (int mf = 0; mf < 2; mf++) {
                    MMA_BF16(c[mf][2*p],   ah[mf], h0, h1);
                    MMA_BF16(c[mf][2*p+1], ah[mf], h2, h3);
                    if (NPB == 2) {
                        MMA_BF16(c[mf][2*p],   ah[mf], l0, l1);
                        MMA_BF16(c[mf][2*p+1], ah[mf], l2, l3);
                    }
                    if (NPA == 2) {
                        MMA_BF16(c[mf][2*p],   al[mf], h0, h1);
                        MMA_BF16(c[mf][2*p+1], al[mf], h2, h3);
                    }
                }
            }
        }
        if (ch + 1 < NCH) CP_WAIT0();
        __syncthreads();
    }

    const int quad = lane >> 2;
    const int tq   = lane & 3;
    #pragma unroll
    for (int mf = 0; mf < 2; mf++) {
        const int r0 = m0 + wm * 32 + mf * 16 + quad;
        const int r1 = r0 + 8;
        float rb0 = 0.f, rb1 = 0.f;
        if (EPI == EPI_SIGR) { rb0 = bias[r0]; rb1 = bias[r1]; }
        #pragma unroll
        for (int nf = 0; nf < 8; nf++) {
            const int col = n0 + wn * 64 + nf * 8 + tq * 2;
            float v0 = c[mf][nf][0], v1 = c[mf][nf][1];
            float v2 = c[mf][nf][2], v3 = c[mf][nf][3];
            if (EPI == EPI_SIGC) {
                float2 bb = *(const float2*)(bias + col);
                v0 = sigmoidf_(v0 + bb.x); v1 = sigmoidf_(v1 + bb.y);
                v2 = sigmoidf_(v2 + bb.x); v3 = sigmoidf_(v3 + bb.y);
            } else if (EPI == EPI_SIGR) {
                v0 = sigmoidf_(v0 + rb0); v1 = sigmoidf_(v1 + rb0);
                v2 = sigmoidf_(v2 + rb1); v3 = sigmoidf_(v3 + rb1);
            }
            if (OUT == OUT_SPLIT) {
                bf16 h0, l0, h1, l1;
                bsplit(v0, h0, l0); bsplit(v1, h1, l1);
                *(bf162*)(Ch + (size_t)r0 * N + col) = __halves2bfloat162(h0, h1);
                *(bf162*)(Cl + (size_t)r0 * N + col) = __halves2bfloat162(l0, l1);
                bsplit(v2, h0, l0); bsplit(v3, h1, l1);
                *(bf162*)(Ch + (size_t)r1 * N + col) = __halves2bfloat162(h0, h1);
                *(bf162*)(Cl + (size_t)r1 * N + col) = __halves2bfloat162(l0, l1);
            } else if (OUT == OUT_HI) {
                *(bf162*)(Ch + (size_t)r0 * N + col) =
                    __halves2bfloat162(__float2bfloat16(v0), __float2bfloat16(v1));
                *(bf162*)(Ch + (size_t)r1 * N + col) =
                    __halves2bfloat162(__float2bfloat16(v2), __float2bfloat16(v3));
            } else {
                *(float2*)(Cf + (size_t)r0 * N + col) = make_float2(v0, v1);
                *(float2*)(Cf + (size_t)r1 * N + col) = make_float2(v2, v3);
            }
        }
    }
}

// ---------------- fused dual GEMM: it + ia' (1-product: x_hi * W_hi) --------
// Warps 0-7 -> it fp32; warps 8-15 -> ia' bf16 hi.
// smem/stage: [Ah, B0h, B1h] x TILEB; 2 stages.
#define DSTAGEB (3 * TILEB)       // 30720
#define DGSMEM  (2 * DSTAGEB)     // 61440

__global__ __launch_bounds__(512, 1)
void mma_gemm_dual(const float* __restrict__ bias_i,
                   const float* __restrict__ bias_ia,
                   const float* __restrict__ ctx)
{
    extern __shared__ char smem[];
    const uint32_t sb = smem_u32(smem);
    const int tid  = threadIdx.x;
    const int lane = tid & 31;
    const int wid  = tid >> 5;
    const int wg   = wid >> 3;        // 0: it, 1: ia
    const int wl   = wid & 7;
    const int wm   = wl & 3;
    const int wn   = wl >> 2;
    const int m0 = blockIdx.y * 128;
    const int n0 = blockIdx.x * 128;
    const int K = HH;

    // loader: 3 tiles x 512 16B-chunks (64 data bytes per row) = 3 cp16/thread
    const bf16* srcp[3];
    uint32_t dstp[3];
    {
        const bf16* baseA_h = (const bf16*)(g_pool + OFF_XH);
        const bf16* baseB0h = (const bf16*)(g_pool + OFF_WIH);
        const bf16* baseB1h = (const bf16*)(g_pool + OFF_WIAH);
        #pragma unroll
        for (int t = 0; t < 3; t++) {
            int chunk = tid + t * 512;
            int tile = chunk >> 9;          // 0..2
            int pos  = chunk & 511;
            int row  = pos >> 2;
            int q    = pos & 3;
            const bf16* bp;
            int rbase;
            switch (tile) {
                case 0: bp = baseA_h; rbase = m0; break;
                case 1: bp = baseB0h; rbase = n0; break;
                default: bp = baseB1h; rbase = n0; break;
            }
            srcp[t] = bp + (size_t)(rbase + row) * K + q * 8;
            dstp[t] = (uint32_t)(tile * TILEB + row * SROW + q * 16);
        }
    }

    const int NCH = K / 32;
    float c[2][8][4] = {};

    {
        #pragma unroll
        for (int t = 0; t < 3; t++)
            cp16(sb + dstp[t], srcp[t]);
        CP_COMMIT();
        CP_WAIT0();
        __syncthreads();
    }

    const uint32_t bofs = (uint32_t)((1 + wg) * TILEB);

    for (int ch = 0; ch < NCH; ch++) {
        if (ch + 1 < NCH) {
            const int k0 = (ch + 1) * 32;
            const uint32_t stg = sb + ((ch + 1) & 1) * DSTAGEB;
            #pragma unroll
            for (int t = 0; t < 3; t++)
                cp16(stg + dstp[t], srcp[t] + k0);
            CP_COMMIT();
        }

        const uint32_t base = sb + (ch & 1) * DSTAGEB;
        #pragma unroll
        for (int ks = 0; ks < 2; ks++) {
            uint32_t ah[2][4];
            #pragma unroll
            for (int mf = 0; mf < 2; mf++) {
                uint32_t addr = base
                    + (uint32_t)((wm * 32 + mf * 16 + (lane & 15)) * SROW)
                    + (uint32_t)(ks * 32 + (lane >> 4) * 16);
                LDSM4(ah[mf][0], ah[mf][1], ah[mf][2], ah[mf][3], addr);
            }
            const int g = lane >> 3;
            #pragma unroll
            for (int p = 0; p < 4; p++) {
                uint32_t addr = base + bofs
                    + (uint32_t)((wn * 64 + p * 16 + ((g & 2) ? 8 : 0) + (lane & 7)) * SROW)
                    + (uint32_t)(ks * 32 + (g & 1) * 16);
                uint32_t h0, h1, h2, h3;
                LDSM4(h0, h1, h2, h3, addr);
                #pragma unroll
                for (int mf = 0; mf < 2; mf++) {
                    MMA_BF16(c[mf][2*p],   ah[mf], h0, h1);
                    MMA_BF16(c[mf][2*p+1], ah[mf], h2, h3);
                }
            }
        }
        if (ch + 1 < NCH) CP_WAIT0();
        __syncthreads();
    }

    const int quad = lane >> 2;
    const int tq   = lane & 3;
    if (wg == 0) {
        float* Cf = (float*)(g_pool + OFF_IT);
        #pragma unroll
        for (int mf = 0; mf < 2; mf++) {
            const int r0 = m0 + wm * 32 + mf * 16 + quad;
            const int r1 = r0 + 8;
            #pragma unroll
            for (int nf = 0; nf < 8; nf++) {
                const int col = n0 + wn * 64 + nf * 8 + tq * 2;
                float2 bb = *(const float2*)(bias_i + col);
                float v0 = sigmoidf_(c[mf][nf][0] + bb.x);
                float v1 = sigmoidf_(c[mf][nf][1] + bb.y);
                float v2 = sigmoidf_(c[mf][nf][2] + bb.x);
                float v3 = sigmoidf_(c[mf][nf][3] + bb.y);
                *(float2*)(Cf + (size_t)r0 * CC + col) = make_float2(v0, v1);
                *(float2*)(Cf + (size_t)r1 * CC + col) = make_float2(v2, v3);
            }
        }
    } else {
        bf16* Ch = (bf16*)(g_pool + OFF_IAH);
        #pragma unroll
        for (int mf = 0; mf < 2; mf++) {
            const int r0 = m0 + wm * 32 + mf * 16 + quad;
            const int r1 = r0 + 8;
            #pragma unroll
            for (int nf = 0; nf < 8; nf++) {
                const int col = n0 + wn * 64 + nf * 8 + tq * 2;
                float2 bb = *(const float2*)(bias_ia + col);
                float2 ss = *(const float2*)(ctx + col);
                float v0 = sigmoidf_(c[mf][nf][0] + bb.x) * ss.x;
                float v1 = sigmoidf_(c[mf][nf][1] + bb.y) * ss.y;
                float v2 = sigmoidf_(c[mf][nf][2] + bb.x) * ss.x;
                float v3 = sigmoidf_(c[mf][nf][3] + bb.y) * ss.y;
                *(bf162*)(Ch + (size_t)r0 * CC + col) =
                    __halves2bfloat162(__float2bfloat16(v0), __float2bfloat16(v1));
                *(bf162*)(Ch + (size_t)r1 * CC + col) =
                    __halves2bfloat162(__float2bfloat16(v2), __float2bfloat16(v3));
            }
        }
    }
}

// ---------------- G7 + fusion: fpart[mblk][c] = sum_rows it * (attn @ lt^T) --
#define FSTAGE (2 * TILEB)
#define F7SMEM (2 * FSTAGE + 4 * 128 * 4)  // 43008

__global__ __launch_bounds__(256, 2)
void mma_gemm_fuse()
{
    const bf16* Ah = (const bf16*)(g_pool + OFF_ATTH);
    const bf16* Bh = (const bf16*)(g_pool + OFF_LTH);
    const float* itp = (const float*)(g_pool + OFF_IT);
    float* fpart = (float*)(g_pool + OFF_FP);

    extern __shared__ char smem[];
    const uint32_t sb = smem_u32(smem);
    float* facc = (float*)(smem + 2 * FSTAGE);
    const int tid  = threadIdx.x;
    const int lane = tid & 31;
    const int wid  = tid >> 5;
    const int wm   = wid & 3;
    const int wn   = wid >> 2;
    const int m0 = blockIdx.y * 128;
    const int n0 = blockIdx.x * 128;
    const int K = LL;

    const int lr = tid >> 1;
    const int lh = tid & 1;
    const bf16* gAh = Ah + (size_t)(m0 + lr) * K + lh * 16;
    const bf16* gBh = Bh + (size_t)(n0 + lr) * K + lh * 16;
    const uint32_t sdst = (uint32_t)(lr * SROW + lh * 32);

    const int NCH = K / 32;
    float c[2][8][4] = {};

    {
        uint32_t d = sb + sdst;
        cp32(d,         gAh);
        cp32(d + TILEB, gBh);
        CP_COMMIT();
        CP_WAIT0();
        __syncthreads();
    }

    for (int ch = 0; ch < NCH; ch++) {
        if (ch + 1 < NCH) {
            const int k0 = (ch + 1) * 32;
            uint32_t d = sb + ((ch + 1) & 1) * FSTAGE + sdst;
            cp32(d,         gAh + k0);
            cp32(d + TILEB, gBh + k0);
            CP_COMMIT();
        }

        const uint32_t base = sb + (ch & 1) * FSTAGE;
        #pragma unroll
        for (int ks = 0; ks < 2; ks++) {
            uint32_t ah[2][4];
            #pragma unroll
            for (int mf = 0; mf < 2; mf++) {
                uint32_t addr = base
                    + (uint32_t)((wm * 32 + mf * 16 + (lane & 15)) * SROW)
                    + (uint32_t)(ks * 32 + (lane >> 4) * 16);
                LDSM4(ah[mf][0], ah[mf][1], ah[mf][2], ah[mf][3], addr);
            }
            const int g = lane >> 3;
            #pragma unroll
            for (int p = 0; p < 4; p++) {
                uint32_t addr = base + TILEB
                    + (uint32_t)((wn * 64 + p * 16 + ((g & 2) ? 8 : 0) + (lane & 7)) * SROW)
                    + (uint32_t)(ks * 32 + (g & 1) * 16);
                uint32_t h0, h1, h2, h3;
                LDSM4(h0, h1, h2, h3, addr);
                #pragma unroll
                for (int mf = 0; mf < 2; mf++) {
                    MMA_BF16(c[mf][2*p],   ah[mf], h0, h1);
                    MMA_BF16(c[mf][2*p+1], ah[mf], h2, h3);
                }
            }
        }
        if (ch + 1 < NCH) CP_WAIT0();
        __syncthreads();
    }

    const int quad = lane >> 2;
    const int tq   = lane & 3;
    float pc[16];
    #pragma unroll
    for (int i = 0; i < 16; i++) pc[i] = 0.0f;
    #pragma unroll
    for (int mf = 0; mf < 2; mf++) {
        const int r0g = m0 + wm * 32 + mf * 16 + quad;
        const int r1g = r0g + 8;
        #pragma unroll
        for (int nf = 0; nf < 8; nf++) {
            const int colg = n0 + wn * 64 + nf * 8 + tq * 2;
            float2 i0 = *(const float2*)(itp + (size_t)r0g * CC + colg);
            float2 i1 = *(const float2*)(itp + (size_t)r1g * CC + colg);
            pc[2*nf]   += c[mf][nf][0] * i0.x + c[mf][nf][2] * i1.x;
            pc[2*nf+1] += c[mf][nf][1] * i0.y + c[mf][nf][3] * i1.y;
        }
    }
    #pragma unroll
    for (int off = 4; off <= 16; off <<= 1)
        #pragma unroll
        for (int i = 0; i < 16; i++)
            pc[i] += __shfl_xor_sync(0xffffffff, pc[i], off);
    if (quad == 0) {
        #pragma unroll
        for (int nf = 0; nf < 8; nf++) {
            const int col = wn * 64 + nf * 8 + tq * 2;
            facc[wm * 128 + col]     = pc[2*nf];
            facc[wm * 128 + col + 1] = pc[2*nf+1];
        }
    }
    __syncthreads();
    if (tid < 128) {
        float s = facc[tid] + facc[128 + tid] + facc[256 + tid] + facc[384 + tid];
        fpart[(size_t)blockIdx.y * CC + n0 + tid] = s;
    }
}

// ---------------- softmax over L=256; writes bf16 attn (hi only) -------------
__global__ __launch_bounds__(256)
void softmax256()
{
    const float* logits = (const float*)(g_pool + OFF_LOGITS);
    bf16* atth = (bf16*)(g_pool + OFF_ATTH);

    const int row = blockIdx.x * 8 + threadIdx.y;
    const int lane = threadIdx.x;
    const float* r = logits + (size_t)row * LL;

    float v[8];
    float mx = -1e30f;
    #pragma unroll
    for (int j = 0; j < 8; j++) {
        v[j] = r[lane + 32 * j];
        mx = fmaxf(mx, v[j]);
    }
    #pragma unroll
    for (int s = 16; s > 0; s >>= 1)
        mx = fmaxf(mx, __shfl_xor_sync(0xffffffff, mx, s));

    float sum = 0.0f;
    #pragma unroll
    for (int j = 0; j < 8; j++) {
        v[j] = __expf(v[j] - mx);
        sum += v[j];
    }
    #pragma unroll
    for (int s = 16; s > 0; s >>= 1)
        sum += __shfl_xor_sync(0xffffffff, sum, s);

    const float inv = 1.0f / sum;
    const size_t ro = (size_t)row * LL;
    #pragma unroll
    for (int j = 0; j < 8; j++)
        atth[ro + lane + 32 * j] = __float2bfloat16(v[j] * inv);
}

// ---------------- fusion reduce: 16 m-blocks per batch -----------------------
__global__ __launch_bounds__(512)
void fusion_reduce()
{
    const float* fp = (const float*)(g_pool + OFF_FP);
    float* fu = (float*)(g_pool + OFF_FU);
    const int b = blockIdx.x, cidx = threadIdx.x;
    float acc = 0.0f;
    #pragma unroll
    for (int k = 0; k < 16; k++)
        acc += fp[((size_t)b * 16 + k) * CC + cidx];
    fu[(size_t)b * CC + cidx] = acc;
}

// ---------------- final: out[b,h] = sum_c fusion[b,c] * Wp[h,c] -------------
__global__ __launch_bounds__(256)
void final_gemm(const float* __restrict__ Wp, float* __restrict__ out)
{
    __shared__ float fs[CC];
    const float* fu = (const float*)(g_pool + OFF_FU);
    const int b = blockIdx.x;
    const int h = blockIdx.y * 256 + threadIdx.x;

    for (int i = threadIdx.x; i < CC; i += 256)
        fs[i] = fu[(size_t)b * CC + i];
    __syncthreads();

    float acc = 0.0f;
    const float4* wp4 = (const float4*)(Wp + (size_t)h * CC);
    const float4* fs4 = (const float4*)fs;
    #pragma unroll 4
    for (int c4 = 0; c4 < CC / 4; c4++) {
        float4 w = wp4[c4], f = fs4[c4];
        acc += w.x * f.x + w.y * f.y + w.z * f.z + w.w * f.w;
    }
    out[(size_t)b * HH + h] = acc;
}

// ---------------- launch ----------------------------------------------------
extern "C" void kernel_launch(void* const* d_in, const int* in_sizes, int n_in,
                              void* d_out, int out_size)
{
    const float* x   = (const float*)d_in[0];
    const float* lab = (const float*)d_in[1];
    const float* Wi  = (const float*)d_in[2];
    const float* bi  = (const float*)d_in[3];
    const float* Wl  = (const float*)d_in[4];
    const float* bl  = (const float*)d_in[5];
    const float* Wia = (const float*)d_in[6];
    const float* bia = (const float*)d_in[7];
    const float* Wla = (const float*)d_in[8];
    const float* bla = (const float*)d_in[9];
    const float* ctx = (const float*)d_in[10];
    const float* Wp  = (const float*)d_in[11];
    float* out = (float*)d_out;

    cudaFuncSetAttribute(mma_gemm<EPI_SIGR, OUT_HI, 2, 2>,    cudaFuncAttributeMaxDynamicSharedMemorySize, GSMEM);
    cudaFuncSetAttribute(mma_gemm<EPI_SIGC, OUT_SPLIT, 2, 2>, cudaFuncAttributeMaxDynamicSharedMemorySize, GSMEM);
    cudaFuncSetAttribute(mma_gemm<EPI_NONE, OUT_F32, 1, 2>,   cudaFuncAttributeMaxDynamicSharedMemorySize, GSMEM);
    cudaFuncSetAttribute(mma_gemm_dual,                        cudaFuncAttributeMaxDynamicSharedMemorySize, DGSMEM);
    cudaFuncSetAttribute(mma_gemm_fuse,                        cudaFuncAttributeMaxDynamicSharedMemorySize, F7SMEM);

    // ---- input splits ----
    ksplit_hi<<<(MROWS * HH / 4 + 255) / 256, 256>>>((const float4*)x,   OFF_XH,   MROWS * HH / 4);
    ksplit_hi<<<(CC * HH / 4 + 255) / 256, 256>>>((const float4*)Wi,  OFF_WIH,  CC * HH / 4);
    ksplit_hi<<<(CC * HH / 4 + 255) / 256, 256>>>((const float4*)Wia, OFF_WIAH, CC * HH / 4);
    ksplit<<<(LL * HH / 4 + 255) / 256, 256>>>((const float4*)lab, OFF_LABH, OFF_LABL, LL * HH / 4);
    ksplit<<<(CC * HH / 4 + 255) / 256, 256>>>((const float4*)Wl,  OFF_WLH,  OFF_WLL,  CC * HH / 4);
    ksplit<<<(CC * HH / 4 + 255) / 256, 256>>>((const float4*)Wla, OFF_WLAH, OFF_WLAL, CC * HH / 4);

    // ---- fused G3+G4 (1-product): it (fp32) and ia' (bf16 hi) ----
    mma_gemm_dual<<<dim3(CC / 128, MROWS / 128), 512, DGSMEM>>>(bi, bia, ctx);

    // ---- G1: ltT[c,l] = sigmoid(Wl @ lab^T + bl[row]), hi-only out ----
    mma_gemm<EPI_SIGR, OUT_HI, 2, 2><<<dim3(LL / 128, CC / 128), 256, GSMEM>>>(
        OFF_WLH, OFF_WLL, OFF_LABH, OFF_LABL, 0, OFF_LTH, 0, CC, LL, HH, bl);

    // ---- G2: la[l,c] = sigmoid(lab @ Wla^T + bla[col]), split out ----
    mma_gemm<EPI_SIGC, OUT_SPLIT, 2, 2><<<dim3(CC / 128, LL / 128), 256, GSMEM>>>(
        OFF_LABH, OFF_LABL, OFF_WLAH, OFF_WLAL, 0, OFF_LAH, OFF_LAL, LL, CC, HH, bla);

    // ---- G5: logits = ia' @ la^T (2-product: iah*lah + iah*lal) ----
    mma_gemm<EPI_NONE, OUT_F32, 1, 2><<<dim3(LL / 128, MROWS / 128), 256, GSMEM>>>(
        OFF_IAH, 0, OFF_LAH, OFF_LAL, OFF_LOGITS, 0, 0, MROWS, LL, CC, nullptr);

    // ---- softmax -> attn (bf16 hi) ----
    softmax256<<<MROWS / 8, dim3(32, 8)>>>();

    // ---- G7 + fusion_partial fused ----
    mma_gemm_fuse<<<dim3(CC / 128, MROWS / 128), 256, F7SMEM>>>();

    // ---- fusion + final projection ----
    fusion_reduce<<<BB, 512>>>();
    final_gemm<<<dim3(BB, HH / 256), 256>>>(Wp, out);
}

// round 13
// speedup vs baseline: 1.8352x; 1.0633x over previous
#include <cuda_runtime.h>
#include <cuda_bf16.h>
#include <cstdint>
#include <cstddef>

// Problem dims (fixed)
#define BB 16
#define SS 2048
#define LL 256
#define HH 768
#define CC 512
#define MROWS (BB*SS)   // 32768

typedef __nv_bfloat16  bf16;
typedef __nv_bfloat162 bf162;

// ---------------- one static scratch pool, byte-addressed -------------------
constexpr size_t SZ_IT     = (size_t)MROWS * CC * 2;        // it as bf16
constexpr size_t SZ_LOGITS = (size_t)MROWS * LL * 4;
constexpr size_t SZ_FP     = (size_t)256 * CC * 4;
constexpr size_t SZ_FU     = (size_t)BB * CC * 4;
constexpr size_t SZ_X2     = (size_t)MROWS * HH * 2;
constexpr size_t SZ_LAB2   = (size_t)LL * HH * 2;
constexpr size_t SZ_WT2    = (size_t)CC * HH * 2;
constexpr size_t SZ_IA2    = (size_t)MROWS * CC * 2;
constexpr size_t SZ_ATT2   = (size_t)MROWS * LL * 2;
constexpr size_t SZ_LC2    = (size_t)LL * CC * 2;

constexpr size_t OFF_IT     = 0;
constexpr size_t OFF_LOGITS = OFF_IT + SZ_IT;
constexpr size_t OFF_FP     = OFF_LOGITS + SZ_LOGITS;
constexpr size_t OFF_FU     = OFF_FP + SZ_FP;
constexpr size_t OFF_XH     = OFF_FU + SZ_FU;
constexpr size_t OFF_LABH   = OFF_XH + SZ_X2;
constexpr size_t OFF_LABL   = OFF_LABH + SZ_LAB2;
constexpr size_t OFF_WIH    = OFF_LABL + SZ_LAB2;
constexpr size_t OFF_WLH    = OFF_WIH + SZ_WT2;
constexpr size_t OFF_WLL    = OFF_WLH + SZ_WT2;
constexpr size_t OFF_WIAH   = OFF_WLL + SZ_WT2;
constexpr size_t OFF_WLAH   = OFF_WIAH + SZ_WT2;
constexpr size_t OFF_WLAL   = OFF_WLAH + SZ_WT2;
constexpr size_t OFF_IAH    = OFF_WLAL + SZ_WT2;
constexpr size_t OFF_ATTH   = OFF_IAH + SZ_IA2;
constexpr size_t OFF_LTH    = OFF_ATTH + SZ_ATT2;
constexpr size_t OFF_LAH    = OFF_LTH + SZ_LC2;
constexpr size_t POOL_BYTES = OFF_LAH + SZ_LC2;

__device__ __align__(16) unsigned char g_pool[POOL_BYTES];

// ---------------- helpers ---------------------------------------------------
__device__ __forceinline__ uint32_t smem_u32(const void* p) {
    uint32_t a;
    asm("{ .reg .u64 t; cvta.to.shared.u64 t, %1; cvt.u32.u64 %0, t; }" : "=r"(a) : "l"(p));
    return a;
}
__device__ __forceinline__ void cp16(uint32_t dst, const void* src) {
    asm volatile("cp.async.cg.shared.global [%0], [%1], 16;" :: "r"(dst), "l"(src) : "memory");
}
__device__ __forceinline__ void cp32(uint32_t dst, const bf16* src) {
    cp16(dst, src);
    cp16(dst + 16, src + 8);
}
#define CP_COMMIT() asm volatile("cp.async.commit_group;" ::: "memory")
#define CP_WAIT0()  asm volatile("cp.async.wait_group 0;"  ::: "memory")

#define LDSM4(R0,R1,R2,R3,ADDR) \
    asm volatile("ldmatrix.sync.aligned.m8n8.x4.shared.b16 {%0,%1,%2,%3}, [%4];" \
                 : "=r"(R0),"=r"(R1),"=r"(R2),"=r"(R3) : "r"(ADDR))

#define MMA_BF16(C,A,B0,B1) \
    asm volatile("mma.sync.aligned.m16n8k16.row.col.f32.bf16.bf16.f32 " \
                 "{%0,%1,%2,%3},{%4,%5,%6,%7},{%8,%9},{%0,%1,%2,%3};" \
                 : "+f"((C)[0]),"+f"((C)[1]),"+f"((C)[2]),"+f"((C)[3]) \
                 : "r"((A)[0]),"r"((A)[1]),"r"((A)[2]),"r"((A)[3]), \
                   "r"(B0),"r"(B1))

__device__ __forceinline__ void bsplit(float v, bf16& h, bf16& l) {
    h = __float2bfloat16(v);
    l = __float2bfloat16(v - __bfloat162float(h));
}
__device__ __forceinline__ float sigmoidf_(float v) {
    return 1.0f / (1.0f + __expf(-v));
}

// ---------------- fp32 -> bf16 splits ----------------------------------------
__global__ __launch_bounds__(256)
void ksplit(const float4* __restrict__ src, size_t oHi, size_t oLo, int n4)
{
    int i = blockIdx.x * 256 + threadIdx.x;
    if (i >= n4) return;
    bf162* hi = (bf162*)(g_pool + oHi);
    bf162* lo = (bf162*)(g_pool + oLo);
    float4 v = src[i];
    bf16 h0, l0, h1, l1, h2, l2, h3, l3;
    bsplit(v.x, h0, l0); bsplit(v.y, h1, l1);
    bsplit(v.z, h2, l2); bsplit(v.w, h3, l3);
    hi[i * 2 + 0] = __halves2bfloat162(h0, h1);
    hi[i * 2 + 1] = __halves2bfloat162(h2, h3);
    lo[i * 2 + 0] = __halves2bfloat162(l0, l1);
    lo[i * 2 + 1] = __halves2bfloat162(l2, l3);
}

__global__ __launch_bounds__(256)
void ksplit_hi(const float4* __restrict__ src, size_t oHi, int n4)
{
    int i = blockIdx.x * 256 + threadIdx.x;
    if (i >= n4) return;
    bf162* hi = (bf162*)(g_pool + oHi);
    float4 v = src[i];
    hi[i * 2 + 0] = __halves2bfloat162(__float2bfloat16(v.x), __float2bfloat16(v.y));
    hi[i * 2 + 1] = __halves2bfloat162(__float2bfloat16(v.z), __float2bfloat16(v.w));
}

// ---------------- shared tile geometry ---------------------------------------
#define SROW  80
#define TILEB (128 * SROW)  // 10240

enum { EPI_NONE = 0, EPI_SIGC = 1, EPI_SIGR = 3 };
enum { OUT_F32 = 0, OUT_SPLIT = 1, OUT_HI = 2 };

// ---------------- generalized bf16 mma GEMM ----------------------------------
#define STAGEB (4 * TILEB)
#define GSMEM (2 * STAGEB)  // 81920

template<int EPI, int OUT, int NPA, int NPB>
__global__ __launch_bounds__(256, 2)
void mma_gemm(size_t oAh, size_t oAl, size_t oBh, size_t oBl,
              size_t oCf, size_t oCh, size_t oCl,
              int M, int N, int K,
              const float* __restrict__ bias)
{
    const bf16* Ah = (const bf16*)(g_pool + oAh);
    const bf16* Al = (const bf16*)(g_pool + oAl);
    const bf16* Bh = (const bf16*)(g_pool + oBh);
    const bf16* Bl = (const bf16*)(g_pool + oBl);
    float* Cf = (float*)(g_pool + oCf);
    bf16* Ch  = (bf16*)(g_pool + oCh);
    bf16* Cl  = (bf16*)(g_pool + oCl);

    extern __shared__ char smem[];
    const uint32_t sb = smem_u32(smem);
    const int tid  = threadIdx.x;
    const int lane = tid & 31;
    const int wid  = tid >> 5;
    const int wm   = wid & 3;
    const int wn   = wid >> 2;
    const int m0 = blockIdx.y * 128;
    const int n0 = blockIdx.x * 128;

    const int lr = tid >> 1;
    const int lh = tid & 1;
    const bf16* gAh = Ah + (size_t)(m0 + lr) * K + lh * 16;
    const bf16* gAl = Al + (size_t)(m0 + lr) * K + lh * 16;
    const bf16* gBh = Bh + (size_t)(n0 + lr) * K + lh * 16;
    const bf16* gBl = Bl + (size_t)(n0 + lr) * K + lh * 16;
    const uint32_t sdst = (uint32_t)(lr * SROW + lh * 32);

    const int NCH = K / 32;
    float c[2][8][4] = {};

    {
        uint32_t d = sb + sdst;
        cp32(d,             gAh);
        if (NPA == 2) cp32(d + TILEB, gAl);
        cp32(d + 2 * TILEB, gBh);
        if (NPB == 2) cp32(d + 3 * TILEB, gBl);
        CP_COMMIT();
        CP_WAIT0();
        __syncthreads();
    }

    for (int ch = 0; ch < NCH; ch++) {
        if (ch + 1 < NCH) {
            const int k0 = (ch + 1) * 32;
            uint32_t d = sb + ((ch + 1) & 1) * STAGEB + sdst;
            cp32(d,             gAh + k0);
            if (NPA == 2) cp32(d + TILEB, gAl + k0);
            cp32(d + 2 * TILEB, gBh + k0);
            if (NPB == 2) cp32(d + 3 * TILEB, gBl + k0);
            CP_COMMIT();
        }

        const uint32_t base = sb + (ch & 1) * STAGEB;
        #pragma unroll
        for (int ks = 0; ks < 2; ks++) {
            uint32_t ah[2][4], al[2][4];
            #pragma unroll
            for (int mf = 0; mf < 2; mf++) {
                uint32_t addr = base
                    + (uint32_t)((wm * 32 + mf * 16 + (lane & 15)) * SROW)
                    + (uint32_t)(ks * 32 + (lane >> 4) * 16);
                LDSM4(ah[mf][0], ah[mf][1], ah[mf][2], ah[mf][3], addr);
                if (NPA == 2)
                    LDSM4(al[mf][0], al[mf][1], al[mf][2], al[mf][3], addr + TILEB);
            }
            const int g = lane >> 3;
            #pragma unroll
            for (int p = 0; p < 4; p++) {
                uint32_t addr = base + 2 * TILEB
                    + (uint32_t)((wn * 64 + p * 16 + ((g & 2) ? 8 : 0) + (lane & 7)) * SROW)
                    + (uint32_t)(ks * 32 + (g & 1) * 16);
                uint32_t h0, h1, h2, h3;
                LDSM4(h0, h1, h2, h3, addr);
                uint32_t l0, l1, l2, l3;
                if (NPB == 2) LDSM4(l0, l1, l2, l3, addr + TILEB);
                #pragma unroll
                for (int mf = 0; mf < 2; mf++) {
                    MMA_BF16(c[mf][2*p],   ah[mf], h0, h1);
                    MMA_BF16(c[mf][2*p+1], ah[mf], h2, h3);
                    if (NPB == 2) {
                        MMA_BF16(c[mf][2*p],   ah[mf], l0, l1);
                        MMA_BF16(c[mf][2*p+1], ah[mf], l2, l3);
                    }
                    if (NPA == 2) {
                        MMA_BF16(c[mf][2*p],   al[mf], h0, h1);
                        MMA_BF16(c[mf][2*p+1], al[mf], h2, h3);
                    }
                }
            }
        }
        if (ch + 1 < NCH) CP_WAIT0();
        __syncthreads();
    }

    const int quad = lane >> 2;
    const int tq   = lane & 3;
    #pragma unroll
    for (int mf = 0; mf < 2; mf++) {
        const int r0 = m0 + wm * 32 + mf * 16 + quad;
        const int r1 = r0 + 8;
        float rb0 = 0.f, rb1 = 0.f;
        if (EPI == EPI_SIGR) { rb0 = bias[r0]; rb1 = bias[r1]; }
        #pragma unroll
        for (int nf = 0; nf < 8; nf++) {
            const int col = n0 + wn * 64 + nf * 8 + tq * 2;
            float v0 = c[mf][nf][0], v1 = c[mf][nf][1];
            float v2 = c[mf][nf][2], v3 = c[mf][nf][3];
            if (EPI == EPI_SIGC) {
                float2 bb = *(const float2*)(bias + col);
                v0 = sigmoidf_(v0 + bb.x); v1 = sigmoidf_(v1 + bb.y);
                v2 = sigmoidf_(v2 + bb.x); v3 = sigmoidf_(v3 + bb.y);
            } else if (EPI == EPI_SIGR) {
                v0 = sigmoidf_(v0 + rb0); v1 = sigmoidf_(v1 + rb0);
                v2 = sigmoidf_(v2 + rb1); v3 = sigmoidf_(v3 + rb1);
            }
            if (OUT == OUT_SPLIT) {
                bf16 h0, l0, h1, l1;
                bsplit(v0, h0, l0); bsplit(v1, h1, l1);
                *(bf162*)(Ch + (size_t)r0 * N + col) = __halves2bfloat162(h0, h1);
                *(bf162*)(Cl + (size_t)r0 * N + col) = __halves2bfloat162(l0, l1);
                bsplit(v2, h0, l0); bsplit(v3, h1, l1);
                *(bf162*)(Ch + (size_t)r1 * N + col) = __halves2bfloat162(h0, h1);
                *(bf162*)(Cl + (size_t)r1 * N + col) = __halves2bfloat162(l0, l1);
            } else if (OUT == OUT_HI) {
                *(bf162*)(Ch + (size_t)r0 * N + col) =
                    __halves2bfloat162(__float2bfloat16(v0), __float2bfloat16(v1));
                *(bf162*)(Ch + (size_t)r1 * N + col) =
                    __halves2bfloat162(__float2bfloat16(v2), __float2bfloat16(v3));
            } else {
                *(float2*)(Cf + (size_t)r0 * N + col) = make_float2(v0, v1);
                *(float2*)(Cf + (size_t)r1 * N + col) = make_float2(v2, v3);
            }
        }
    }
}

// ---------------- fused dual GEMM: it(bf16) + ia'(bf16) (1-product) ----------
#define DSTAGEB (3 * TILEB)       // 30720
#define DGSMEM  (2 * DSTAGEB)     // 61440

__global__ __launch_bounds__(512, 1)
void mma_gemm_dual(const float* __restrict__ bias_i,
                   const float* __restrict__ bias_ia,
                   const float* __restrict__ ctx)
{
    extern __shared__ char smem[];
    const uint32_t sb = smem_u32(smem);
    const int tid  = threadIdx.x;
    const int lane = tid & 31;
    const int wid  = tid >> 5;
    const int wg   = wid >> 3;        // 0: it, 1: ia
    const int wl   = wid & 7;
    const int wm   = wl & 3;
    const int wn   = wl >> 2;
    const int m0 = blockIdx.y * 128;
    const int n0 = blockIdx.x * 128;
    const int K = HH;

    const bf16* srcp[3];
    uint32_t dstp[3];
    {
        const bf16* baseA_h = (const bf16*)(g_pool + OFF_XH);
        const bf16* baseB0h = (const bf16*)(g_pool + OFF_WIH);
        const bf16* baseB1h = (const bf16*)(g_pool + OFF_WIAH);
        #pragma unroll
        for (int t = 0; t < 3; t++) {
            int chunk = tid + t * 512;
            int tile = chunk >> 9;
            int pos  = chunk & 511;
            int row  = pos >> 2;
            int q    = pos & 3;
            const bf16* bp;
            int rbase;
            switch (tile) {
                case 0: bp = baseA_h; rbase = m0; break;
                case 1: bp = baseB0h; rbase = n0; break;
                default: bp = baseB1h; rbase = n0; break;
            }
            srcp[t] = bp + (size_t)(rbase + row) * K + q * 8;
            dstp[t] = (uint32_t)(tile * TILEB + row * SROW + q * 16);
        }
    }

    const int NCH = K / 32;
    float c[2][8][4] = {};

    {
        #pragma unroll
        for (int t = 0; t < 3; t++)
            cp16(sb + dstp[t], srcp[t]);
        CP_COMMIT();
        CP_WAIT0();
        __syncthreads();
    }

    const uint32_t bofs = (uint32_t)((1 + wg) * TILEB);

    for (int ch = 0; ch < NCH; ch++) {
        if (ch + 1 < NCH) {
            const int k0 = (ch + 1) * 32;
            const uint32_t stg = sb + ((ch + 1) & 1) * DSTAGEB;
            #pragma unroll
            for (int t = 0; t < 3; t++)
                cp16(stg + dstp[t], srcp[t] + k0);
            CP_COMMIT();
        }

        const uint32_t base = sb + (ch & 1) * DSTAGEB;
        #pragma unroll
        for (int ks = 0; ks < 2; ks++) {
            uint32_t ah[2][4];
            #pragma unroll
            for (int mf = 0; mf < 2; mf++) {
                uint32_t addr = base
                    + (uint32_t)((wm * 32 + mf * 16 + (lane & 15)) * SROW)
                    + (uint32_t)(ks * 32 + (lane >> 4) * 16);
                LDSM4(ah[mf][0], ah[mf][1], ah[mf][2], ah[mf][3], addr);
            }
            const int g = lane >> 3;
            #pragma unroll
            for (int p = 0; p < 4; p++) {
                uint32_t addr = base + bofs
                    + (uint32_t)((wn * 64 + p * 16 + ((g & 2) ? 8 : 0) + (lane & 7)) * SROW)
                    + (uint32_t)(ks * 32 + (g & 1) * 16);
                uint32_t h0, h1, h2, h3;
                LDSM4(h0, h1, h2, h3, addr);
                #pragma unroll
                for (int mf = 0; mf < 2; mf++) {
                    MMA_BF16(c[mf][2*p],   ah[mf], h0, h1);
                    MMA_BF16(c[mf][2*p+1], ah[mf], h2, h3);
                }
            }
        }
        if (ch + 1 < NCH) CP_WAIT0();
        __syncthreads();
    }

    const int quad = lane >> 2;
    const int tq   = lane & 3;
    if (wg == 0) {
        bf16* Ch = (bf16*)(g_pool + OFF_IT);
        #pragma unroll
        for (int mf = 0; mf < 2; mf++) {
            const int r0 = m0 + wm * 32 + mf * 16 + quad;
            const int r1 = r0 + 8;
            #pragma unroll
            for (int nf = 0; nf < 8; nf++) {
                const int col = n0 + wn * 64 + nf * 8 + tq * 2;
                float2 bb = *(const float2*)(bias_i + col);
                float v0 = sigmoidf_(c[mf][nf][0] + bb.x);
                float v1 = sigmoidf_(c[mf][nf][1] + bb.y);
                float v2 = sigmoidf_(c[mf][nf][2] + bb.x);
                float v3 = sigmoidf_(c[mf][nf][3] + bb.y);
                *(bf162*)(Ch + (size_t)r0 * CC + col) =
                    __halves2bfloat162(__float2bfloat16(v0), __float2bfloat16(v1));
                *(bf162*)(Ch + (size_t)r1 * CC + col) =
                    __halves2bfloat162(__float2bfloat16(v2), __float2bfloat16(v3));
            }
        }
    } else {
        bf16* Ch = (bf16*)(g_pool + OFF_IAH);
        #pragma unroll
        for (int mf = 0; mf < 2; mf++) {
            const int r0 = m0 + wm * 32 + mf * 16 + quad;
            const int r1 = r0 + 8;
            #pragma unroll
            for (int nf = 0; nf < 8; nf++) {
                const int col = n0 + wn * 64 + nf * 8 + tq * 2;
                float2 bb = *(const float2*)(bias_ia + col);
                float2 ss = *(const float2*)(ctx + col);
                float v0 = sigmoidf_(c[mf][nf][0] + bb.x) * ss.x;
                float v1 = sigmoidf_(c[mf][nf][1] + bb.y) * ss.y;
                float v2 = sigmoidf_(c[mf][nf][2] + bb.x) * ss.x;
                float v3 = sigmoidf_(c[mf][nf][3] + bb.y) * ss.y;
                *(bf162*)(Ch + (size_t)r0 * CC + col) =
                    __halves2bfloat162(__float2bfloat16(v0), __float2bfloat16(v1));
                *(bf162*)(Ch + (size_t)r1 * CC + col) =
                    __halves2bfloat162(__float2bfloat16(v2), __float2bfloat16(v3));
            }
        }
    }
}

// ---------------- G7 + fusion: fpart[mblk][c] = sum_rows it * (attn @ lt^T) --
#define FSTAGE (2 * TILEB)
#define F7SMEM (2 * FSTAGE + 4 * 128 * 4)  // 43008

__global__ __launch_bounds__(256, 2)
void mma_gemm_fuse()
{
    const bf16* Ah = (const bf16*)(g_pool + OFF_ATTH);
    const bf16* Bh = (const bf16*)(g_pool + OFF_LTH);
    const bf16* itp = (const bf16*)(g_pool + OFF_IT);
    float* fpart = (float*)(g_pool + OFF_FP);

    extern __shared__ char smem[];
    const uint32_t sb = smem_u32(smem);
    float* facc = (float*)(smem + 2 * FSTAGE);
    const int tid  = threadIdx.x;
    const int lane = tid & 31;
    const int wid  = tid >> 5;
    const int wm   = wid & 3;
    const int wn   = wid >> 2;
    const int m0 = blockIdx.y * 128;
    const int n0 = blockIdx.x * 128;
    const int K = LL;

    const int lr = tid >> 1;
    const int lh = tid & 1;
    const bf16* gAh = Ah + (size_t)(m0 + lr) * K + lh * 16;
    const bf16* gBh = Bh + (size_t)(n0 + lr) * K + lh * 16;
    const uint32_t sdst = (uint32_t)(lr * SROW + lh * 32);

    const int NCH = K / 32;
    float c[2][8][4] = {};

    {
        uint32_t d = sb + sdst;
        cp32(d,         gAh);
        cp32(d + TILEB, gBh);
        CP_COMMIT();
        CP_WAIT0();
        __syncthreads();
    }

    for (int ch = 0; ch < NCH; ch++) {
        if (ch + 1 < NCH) {
            const int k0 = (ch + 1) * 32;
            uint32_t d = sb + ((ch + 1) & 1) * FSTAGE + sdst;
            cp32(d,         gAh + k0);
            cp32(d + TILEB, gBh + k0);
            CP_COMMIT();
        }

        const uint32_t base = sb + (ch & 1) * FSTAGE;
        #pragma unroll
        for (int ks = 0; ks < 2; ks++) {
            uint32_t ah[2][4];
            #pragma unroll
            for (int mf = 0; mf < 2; mf++) {
                uint32_t addr = base
                    + (uint32_t)((wm * 32 + mf * 16 + (lane & 15)) * SROW)
                    + (uint32_t)(ks * 32 + (lane >> 4) * 16);
                LDSM4(ah[mf][0], ah[mf][1], ah[mf][2], ah[mf][3], addr);
            }
            const int g = lane >> 3;
            #pragma unroll
            for (int p = 0; p < 4; p++) {
                uint32_t addr = base + TILEB
                    + (uint32_t)((wn * 64 + p * 16 + ((g & 2) ? 8 : 0) + (lane & 7)) * SROW)
                    + (uint32_t)(ks * 32 + (g & 1) * 16);
                uint32_t h0, h1, h2, h3;
                LDSM4(h0, h1, h2, h3, addr);
                #pragma unroll
                for (int mf = 0; mf < 2; mf++) {
                    MMA_BF16(c[mf][2*p],   ah[mf], h0, h1);
                    MMA_BF16(c[mf][2*p+1], ah[mf], h2, h3);
                }
            }
        }
        if (ch + 1 < NCH) CP_WAIT0();
        __syncthreads();
    }

    const int quad = lane >> 2;
    const int tq   = lane & 3;
    float pc[16];
    #pragma unroll
    for (int i = 0; i < 16; i++) pc[i] = 0.0f;
    #pragma unroll
    for (int mf = 0; mf < 2; mf++) {
        const int r0g = m0 + wm * 32 + mf * 16 + quad;
        const int r1g = r0g + 8;
        #pragma unroll
        for (int nf = 0; nf < 8; nf++) {
            const int colg = n0 + wn * 64 + nf * 8 + tq * 2;
            float2 i0 = __bfloat1622float2(*(const bf162*)(itp + (size_t)r0g * CC + colg));
            float2 i1 = __bfloat1622float2(*(const bf162*)(itp + (size_t)r1g * CC + colg));
            pc[2*nf]   += c[mf][nf][0] * i0.x + c[mf][nf][2] * i1.x;
            pc[2*nf+1] += c[mf][nf][1] * i0.y + c[mf][nf][3] * i1.y;
        }
    }
    #pragma unroll
    for (int off = 4; off <= 16; off <<= 1)
        #pragma unroll
        for (int i = 0; i < 16; i++)
            pc[i] += __shfl_xor_sync(0xffffffff, pc[i], off);
    if (quad == 0) {
        #pragma unroll
        for (int nf = 0; nf < 8; nf++) {
            const int col = wn * 64 + nf * 8 + tq * 2;
            facc[wm * 128 + col]     = pc[2*nf];
            facc[wm * 128 + col + 1] = pc[2*nf+1];
        }
    }
    __syncthreads();
    if (tid < 128) {
        float s = facc[tid] + facc[128 + tid] + facc[256 + tid] + facc[384 + tid];
        fpart[(size_t)blockIdx.y * CC + n0 + tid] = s;
    }
}

// ---------------- softmax over L=256; writes bf16 attn (hi only) -------------
__global__ __launch_bounds__(256)
void softmax256()
{
    const float* logits = (const float*)(g_pool + OFF_LOGITS);
    bf16* atth = (bf16*)(g_pool + OFF_ATTH);

    const int row = blockIdx.x * 8 + threadIdx.y;
    const int lane = threadIdx.x;
    const float* r = logits + (size_t)row * LL;

    float v[8];
    float mx = -1e30f;
    #pragma unroll
    for (int j = 0; j < 8; j++) {
        v[j] = r[lane + 32 * j];
        mx = fmaxf(mx, v[j]);
    }
    #pragma unroll
    for (int s = 16; s > 0; s >>= 1)
        mx = fmaxf(mx, __shfl_xor_sync(0xffffffff, mx, s));

    float sum = 0.0f;
    #pragma unroll
    for (int j = 0; j < 8; j++) {
        v[j] = __expf(v[j] - mx);
        sum += v[j];
    }
    #pragma unroll
    for (int s = 16; s > 0; s >>= 1)
        sum += __shfl_xor_sync(0xffffffff, sum, s);

    const float inv = 1.0f / sum;
    const size_t ro = (size_t)row * LL;
    #pragma unroll
    for (int j = 0; j < 8; j++)
        atth[ro + lane + 32 * j] = __float2bfloat16(v[j] * inv);
}

// ---------------- fusion reduce: 16 m-blocks per batch -----------------------
__global__ __launch_bounds__(512)
void fusion_reduce()
{
    const float* fp = (const float*)(g_pool + OFF_FP);
    float* fu = (float*)(g_pool + OFF_FU);
    const int b = blockIdx.x, cidx = threadIdx.x;
    float acc = 0.0f;
    #pragma unroll
    for (int k = 0; k < 16; k++)
        acc += fp[((size_t)b * 16 + k) * CC + cidx];
    fu[(size_t)b * CC + cidx] = acc;
}

// ---------------- final: out[b,h] = sum_c fusion[b,c] * Wp[h,c] -------------
__global__ __launch_bounds__(256)
void final_gemm(const float* __restrict__ Wp, float* __restrict__ out)
{
    __shared__ float fs[CC];
    const float* fu = (const float*)(g_pool + OFF_FU);
    const int b = blockIdx.x;
    const int h = blockIdx.y * 256 + threadIdx.x;

    for (int i = threadIdx.x; i < CC; i += 256)
        fs[i] = fu[(size_t)b * CC + i];
    __syncthreads();

    float acc = 0.0f;
    const float4* wp4 = (const float4*)(Wp + (size_t)h * CC);
    const float4* fs4 = (const float4*)fs;
    #pragma unroll 4
    for (int c4 = 0; c4 < CC / 4; c4++) {
        float4 w = wp4[c4], f = fs4[c4];
        acc += w.x * f.x + w.y * f.y + w.z * f.z + w.w * f.w;
    }
    out[(size_t)b * HH + h] = acc;
}

// ---------------- launch ----------------------------------------------------
extern "C" void kernel_launch(void* const* d_in, const int* in_sizes, int n_in,
                              void* d_out, int out_size)
{
    const float* x   = (const float*)d_in[0];
    const float* lab = (const float*)d_in[1];
    const float* Wi  = (const float*)d_in[2];
    const float* bi  = (const float*)d_in[3];
    const float* Wl  = (const float*)d_in[4];
    const float* bl  = (const float*)d_in[5];
    const float* Wia = (const float*)d_in[6];
    const float* bia = (const float*)d_in[7];
    const float* Wla = (const float*)d_in[8];
    const float* bla = (const float*)d_in[9];
    const float* ctx = (const float*)d_in[10];
    const float* Wp  = (const float*)d_in[11];
    float* out = (float*)d_out;

    cudaFuncSetAttribute(mma_gemm<EPI_SIGR, OUT_HI, 2, 2>, cudaFuncAttributeMaxDynamicSharedMemorySize, GSMEM);
    cudaFuncSetAttribute(mma_gemm<EPI_SIGC, OUT_HI, 2, 2>, cudaFuncAttributeMaxDynamicSharedMemorySize, GSMEM);
    cudaFuncSetAttribute(mma_gemm<EPI_NONE, OUT_F32, 1, 1>, cudaFuncAttributeMaxDynamicSharedMemorySize, GSMEM);
    cudaFuncSetAttribute(mma_gemm_dual, cudaFuncAttributeMaxDynamicSharedMemorySize, DGSMEM);
    cudaFuncSetAttribute(mma_gemm_fuse, cudaFuncAttributeMaxDynamicSharedMemorySize, F7SMEM);

    // ---- input splits ----
    ksplit_hi<<<(MROWS * HH / 4 + 255) / 256, 256>>>((const float4*)x,   OFF_XH,   MROWS * HH / 4);
    ksplit_hi<<<(CC * HH / 4 + 255) / 256, 256>>>((const float4*)Wi,  OFF_WIH,  CC * HH / 4);
    ksplit_hi<<<(CC * HH / 4 + 255) / 256, 256>>>((const float4*)Wia, OFF_WIAH, CC * HH / 4);
    ksplit<<<(LL * HH / 4 + 255) / 256, 256>>>((const float4*)lab, OFF_LABH, OFF_LABL, LL * HH / 4);
    ksplit<<<(CC * HH / 4 + 255) / 256, 256>>>((const float4*)Wl,  OFF_WLH,  OFF_WLL,  CC * HH / 4);
    ksplit<<<(CC * HH / 4 + 255) / 256, 256>>>((const float4*)Wla, OFF_WLAH, OFF_WLAL, CC * HH / 4);

    // ---- fused G3+G4 (1-product): it (bf16) and ia' (bf16) ----
    mma_gemm_dual<<<dim3(CC / 128, MROWS / 128), 512, DGSMEM>>>(bi, bia, ctx);

    // ---- G1: ltT[c,l] = sigmoid(Wl @ lab^T + bl[row]), hi-only out ----
    mma_gemm<EPI_SIGR, OUT_HI, 2, 2><<<dim3(LL / 128, CC / 128), 256, GSMEM>>>(
        OFF_WLH, OFF_WLL, OFF_LABH, OFF_LABL, 0, OFF_LTH, 0, CC, LL, HH, bl);

    // ---- G2: la[l,c] = sigmoid(lab @ Wla^T + bla[col]), hi-only out ----
    mma_gemm<EPI_SIGC, OUT_HI, 2, 2><<<dim3(CC / 128, LL / 128), 256, GSMEM>>>(
        OFF_LABH, OFF_LABL, OFF_WLAH, OFF_WLAL, 0, OFF_LAH, 0, LL, CC, HH, bla);

    // ---- G5: logits = ia' @ la^T (1-product) ----
    mma_gemm<EPI_NONE, OUT_F32, 1, 1><<<dim3(LL / 128, MROWS / 128), 256, GSMEM>>>(
        OFF_IAH, 0, OFF_LAH, 0, OFF_LOGITS, 0, 0, MROWS, LL, CC, nullptr);

    // ---- softmax -> attn (bf16 hi) ----
    softmax256<<<MROWS / 8, dim3(32, 8)>>>();

    // ---- G7 + fusion_partial fused ----
    mma_gemm_fuse<<<dim3(CC / 128, MROWS / 128), 256, F7SMEM>>>();

    // ---- fusion + final projection ----
    fusion_reduce<<<BB, 512>>>();
    final_gemm<<<dim3(BB, HH / 256), 256>>>(Wp, out);
}